// round 5
// baseline (speedup 1.0000x reference)
#include <cuda_runtime.h>
#include <cuda_bf16.h>
#include <math.h>

#define NN 100000
#define EE 1600000
#define FIN 512
#define H1 8
#define C1 8
#define HC 64
#define NC 40
#define ETOT (EE + NN)
#define NEG_SLOPE 0.2f
#define NBLK 98   // ceil(NN/1024)

// ---------------- scratch ----------------
__device__ float g_h1[NN * HC];
__device__ float g_as1[NN * H1];
__device__ float g_ad1[NN * H1];
__device__ float g_o1[NN * HC];
__device__ float g_z[NN * NC];
__device__ float g_as2[NN];
__device__ float g_ad2[NN];
__device__ int   g_src[ETOT];
__device__ int   g_dst[ETOT];
__device__ int   g_deg[NN];
__device__ int   g_row[NN + 1];
__device__ int   g_cursor[NN];
__device__ int   g_bsum[NBLK];
__device__ int   g_csr[ETOT];
__device__ int   g_is64;
__device__ unsigned short g_W1T_hi[HC * FIN];
__device__ unsigned short g_W1T_lo[HC * FIN];

__device__ __forceinline__ float lrelu(float x) {
    return x > 0.0f ? x : NEG_SLOPE * x;
}

__device__ __forceinline__ void split_bf16(float v, unsigned short& hi, unsigned short& lo) {
    __nv_bfloat16 h = __float2bfloat16(v);
    float r = v - __bfloat162float(h);
    __nv_bfloat16 l = __float2bfloat16(r);
    hi = __bfloat16_as_ushort(h);
    lo = __bfloat16_as_ushort(l);
}

__device__ __forceinline__ void mma_bf16(float* c, const unsigned* a, const unsigned* b) {
    asm volatile(
        "mma.sync.aligned.m16n8k16.row.col.f32.bf16.bf16.f32 "
        "{%0,%1,%2,%3},{%4,%5,%6,%7},{%8,%9},{%0,%1,%2,%3};"
        : "+f"(c[0]), "+f"(c[1]), "+f"(c[2]), "+f"(c[3])
        : "r"(a[0]), "r"(a[1]), "r"(a[2]), "r"(a[3]), "r"(b[0]), "r"(b[1]));
}

// ---------------- init ----------------
__global__ void k_init() {
    int i = blockIdx.x * blockDim.x + threadIdx.x;
    if (i < NN) g_deg[i] = 0;
    if (i == 0) g_is64 = 1;
}

// ---------------- edge dtype probe + conversion + degree count ----------------
__global__ void k_detect(const void* __restrict__ ei) {
    int i = blockIdx.x * blockDim.x + threadIdx.x;
    const long long* p = (const long long*)ei;
    long long v = p[i];
    if (v < 0 || v >= NN) atomicAnd(&g_is64, 0);
}

__global__ void k_convert(const void* __restrict__ ei) {
    int idx = blockIdx.x * blockDim.x + threadIdx.x;
    if (idx >= ETOT) return;
    int s, d;
    if (idx < EE) {
        if (g_is64) {
            const long long* p = (const long long*)ei;
            s = (int)p[idx];
            d = (int)p[EE + idx];
        } else {
            const int* p = (const int*)ei;
            s = p[idx];
            d = p[EE + idx];
        }
    } else {
        s = d = idx - EE;
    }
    s = min(max(s, 0), NN - 1);
    d = min(max(d, 0), NN - 1);
    g_src[idx] = s;
    g_dst[idx] = d;
    atomicAdd(&g_deg[d], 1);
}

// ---------------- exclusive scan of degrees ----------------
__global__ void k_scan1() {
    __shared__ int sh[1024];
    int tid = threadIdx.x;
    int i = blockIdx.x * 1024 + tid;
    int v = (i < NN) ? g_deg[i] : 0;
    sh[tid] = v;
    __syncthreads();
    #pragma unroll
    for (int off = 1; off < 1024; off <<= 1) {
        int t = (tid >= off) ? sh[tid - off] : 0;
        __syncthreads();
        sh[tid] += t;
        __syncthreads();
    }
    if (i < NN) g_row[i] = sh[tid] - v;
    if (tid == 1023) g_bsum[blockIdx.x] = sh[1023];
}

__global__ void k_scan2() {
    if (threadIdx.x == 0) {
        int acc = 0;
        for (int b = 0; b < NBLK; b++) { int t = g_bsum[b]; g_bsum[b] = acc; acc += t; }
        g_row[NN] = acc;
    }
}

__global__ void k_scan3() {
    int i = blockIdx.x * blockDim.x + threadIdx.x;
    if (i < NN) {
        int r = g_row[i] + g_bsum[i >> 10];
        g_row[i] = r;
        g_cursor[i] = r;
    }
}

__global__ void k_scatter() {
    int idx = blockIdx.x * blockDim.x + threadIdx.x;
    if (idx >= ETOT) return;
    int d = g_dst[idx];
    int pos = atomicAdd(&g_cursor[d], 1);
    g_csr[pos] = g_src[idx];
}

// ---------------- W1 split/transpose ----------------
__global__ void k_prepW(const float* __restrict__ W1) {
    int i = blockIdx.x * blockDim.x + threadIdx.x;
    if (i >= FIN * HC) return;
    int k = i / HC, n = i % HC;
    unsigned short hi, lo;
    split_bf16(W1[i], hi, lo);
    g_W1T_hi[n * FIN + k] = hi;
    g_W1T_lo[n * FIN + k] = lo;
}

// ---------------- GEMM1 (tensor cores, bf16x3, register double-buffer) ----------------
#define ASTR 40
__global__ __launch_bounds__(256) void k_gemm1(const float* __restrict__ x) {
    __shared__ unsigned short As_hi[128 * ASTR];
    __shared__ unsigned short As_lo[128 * ASTR];
    __shared__ unsigned short Bs_hi[64 * ASTR];
    __shared__ unsigned short Bs_lo[64 * ASTR];

    const int t = threadIdx.x;
    const int bm0 = blockIdx.x * 128;
    const int warp = t >> 5;
    const int lane = t & 31;
    const int g = lane >> 2;
    const int q = lane & 3;
    const int warp_m = warp >> 1;
    const int warp_n = warp & 1;
    const int brow = t >> 2;
    const int bseg = t & 3;

    float acc[2][4][4];
    #pragma unroll
    for (int i = 0; i < 2; i++)
        #pragma unroll
        for (int j = 0; j < 4; j++)
            #pragma unroll
            for (int r = 0; r < 4; r++) acc[i][j][r] = 0.f;

    float4 ra[4];
    uint4 rbh, rbl;

    // prologue: load k0 = 0
    #pragma unroll
    for (int i = 0; i < 4; i++) {
        int idx = i * 256 + t;
        int row = idx >> 3;
        int col = (idx & 7) * 4;
        int gr = bm0 + row;
        ra[i] = (gr < NN) ? *(const float4*)(x + (long)gr * FIN + col)
                          : make_float4(0.f, 0.f, 0.f, 0.f);
    }
    rbh = *(const uint4*)&g_W1T_hi[brow * FIN + bseg * 8];
    rbl = *(const uint4*)&g_W1T_lo[brow * FIN + bseg * 8];

    for (int k0 = 0; k0 < FIN; k0 += 32) {
        // ---- store staged tile to smem (split fp32 -> bf16 hi/lo) ----
        #pragma unroll
        for (int i = 0; i < 4; i++) {
            int idx = i * 256 + t;
            int row = idx >> 3;
            int col = (idx & 7) * 4;
            unsigned short h0, l0, h1_, l1_, h2, l2, h3, l3;
            split_bf16(ra[i].x, h0, l0);
            split_bf16(ra[i].y, h1_, l1_);
            split_bf16(ra[i].z, h2, l2);
            split_bf16(ra[i].w, h3, l3);
            unsigned* ph = (unsigned*)&As_hi[row * ASTR + col];
            unsigned* pl = (unsigned*)&As_lo[row * ASTR + col];
            ph[0] = (unsigned)h0 | ((unsigned)h1_ << 16);
            ph[1] = (unsigned)h2 | ((unsigned)h3 << 16);
            pl[0] = (unsigned)l0 | ((unsigned)l1_ << 16);
            pl[1] = (unsigned)l2 | ((unsigned)l3 << 16);
        }
        *(uint4*)&Bs_hi[brow * ASTR + bseg * 8] = rbh;
        *(uint4*)&Bs_lo[brow * ASTR + bseg * 8] = rbl;
        __syncthreads();

        // ---- prefetch next tile into registers (latency hides under MMA) ----
        int kn = k0 + 32;
        if (kn < FIN) {
            #pragma unroll
            for (int i = 0; i < 4; i++) {
                int idx = i * 256 + t;
                int row = idx >> 3;
                int col = (idx & 7) * 4;
                int gr = bm0 + row;
                ra[i] = (gr < NN) ? *(const float4*)(x + (long)gr * FIN + kn + col)
                                  : make_float4(0.f, 0.f, 0.f, 0.f);
            }
            rbh = *(const uint4*)&g_W1T_hi[brow * FIN + kn + bseg * 8];
            rbl = *(const uint4*)&g_W1T_lo[brow * FIN + kn + bseg * 8];
        }

        // ---- compute ----
        #pragma unroll
        for (int ka = 0; ka < 2; ka++) {
            const int kc = ka * 16;
            unsigned a_hi[2][4], a_lo[2][4], b_hi[4][2], b_lo[4][2];
            #pragma unroll
            for (int ma = 0; ma < 2; ma++) {
                int r0 = warp_m * 32 + ma * 16;
                a_hi[ma][0] = *(const unsigned*)&As_hi[(r0 + g) * ASTR + kc + 2 * q];
                a_hi[ma][1] = *(const unsigned*)&As_hi[(r0 + g + 8) * ASTR + kc + 2 * q];
                a_hi[ma][2] = *(const unsigned*)&As_hi[(r0 + g) * ASTR + kc + 2 * q + 8];
                a_hi[ma][3] = *(const unsigned*)&As_hi[(r0 + g + 8) * ASTR + kc + 2 * q + 8];
                a_lo[ma][0] = *(const unsigned*)&As_lo[(r0 + g) * ASTR + kc + 2 * q];
                a_lo[ma][1] = *(const unsigned*)&As_lo[(r0 + g + 8) * ASTR + kc + 2 * q];
                a_lo[ma][2] = *(const unsigned*)&As_lo[(r0 + g) * ASTR + kc + 2 * q + 8];
                a_lo[ma][3] = *(const unsigned*)&As_lo[(r0 + g + 8) * ASTR + kc + 2 * q + 8];
            }
            #pragma unroll
            for (int na = 0; na < 4; na++) {
                int n0 = warp_n * 32 + na * 8;
                b_hi[na][0] = *(const unsigned*)&Bs_hi[(n0 + g) * ASTR + kc + 2 * q];
                b_hi[na][1] = *(const unsigned*)&Bs_hi[(n0 + g) * ASTR + kc + 2 * q + 8];
                b_lo[na][0] = *(const unsigned*)&Bs_lo[(n0 + g) * ASTR + kc + 2 * q];
                b_lo[na][1] = *(const unsigned*)&Bs_lo[(n0 + g) * ASTR + kc + 2 * q + 8];
            }
            #pragma unroll
            for (int ma = 0; ma < 2; ma++)
                #pragma unroll
                for (int na = 0; na < 4; na++) {
                    mma_bf16(acc[ma][na], a_hi[ma], b_hi[na]);
                    mma_bf16(acc[ma][na], a_hi[ma], b_lo[na]);
                    mma_bf16(acc[ma][na], a_lo[ma], b_hi[na]);
                }
        }
        __syncthreads();
    }

    #pragma unroll
    for (int ma = 0; ma < 2; ma++) {
        int r0 = bm0 + warp_m * 32 + ma * 16 + g;
        #pragma unroll
        for (int na = 0; na < 4; na++) {
            int c = warp_n * 32 + na * 8 + 2 * q;
            if (r0 < NN)
                *(float2*)(g_h1 + (long)r0 * HC + c) = make_float2(acc[ma][na][0], acc[ma][na][1]);
            if (r0 + 8 < NN)
                *(float2*)(g_h1 + (long)(r0 + 8) * HC + c) = make_float2(acc[ma][na][2], acc[ma][na][3]);
        }
    }
}

// ---------------- per-node attention logits, layer 1 ----------------
__global__ void k_alpha1(const float* __restrict__ a_s, const float* __restrict__ a_d) {
    int i = blockIdx.x * blockDim.x + threadIdx.x;
    if (i >= NN * H1) return;
    int n = i >> 3, h = i & 7;
    const float* hp = g_h1 + (long)n * HC + h * C1;
    float s = 0.f, d = 0.f;
    #pragma unroll
    for (int c = 0; c < C1; c++) {
        float v = hp[c];
        s = fmaf(v, a_s[h * C1 + c], s);
        d = fmaf(v, a_d[h * C1 + c], d);
    }
    g_as1[i] = s;
    g_ad1[i] = d;
}

// ---------------- layer-1 CSR aggregation (warp/node, unroll x4) ----------------
__global__ void k_agg1(const float* __restrict__ b1) {
    int warp = (blockIdx.x * blockDim.x + threadIdx.x) >> 5;
    if (warp >= NN) return;
    int lane = threadIdx.x & 31;
    int n = warp;
    int h = lane >> 2;
    float adh = g_ad1[n * H1 + h];
    int beg = g_row[n], end = g_row[n + 1];
    float sum_p = 0.f, acc0 = 0.f, acc1 = 0.f;
    int j = beg;
    for (; j + 4 <= end; j += 4) {
        int s0 = g_csr[j], s1 = g_csr[j + 1], s2 = g_csr[j + 2], s3 = g_csr[j + 3];
        float a0 = g_as1[s0 * H1 + h];
        float a1 = g_as1[s1 * H1 + h];
        float a2 = g_as1[s2 * H1 + h];
        float a3 = g_as1[s3 * H1 + h];
        float2 v0 = *(const float2*)(g_h1 + (long)s0 * HC + 2 * lane);
        float2 v1 = *(const float2*)(g_h1 + (long)s1 * HC + 2 * lane);
        float2 v2 = *(const float2*)(g_h1 + (long)s2 * HC + 2 * lane);
        float2 v3 = *(const float2*)(g_h1 + (long)s3 * HC + 2 * lane);
        float p0 = __expf(lrelu(a0 + adh));
        float p1 = __expf(lrelu(a1 + adh));
        float p2 = __expf(lrelu(a2 + adh));
        float p3 = __expf(lrelu(a3 + adh));
        sum_p += (p0 + p1) + (p2 + p3);
        acc0 = fmaf(p0, v0.x, acc0); acc1 = fmaf(p0, v0.y, acc1);
        acc0 = fmaf(p1, v1.x, acc0); acc1 = fmaf(p1, v1.y, acc1);
        acc0 = fmaf(p2, v2.x, acc0); acc1 = fmaf(p2, v2.y, acc1);
        acc0 = fmaf(p3, v3.x, acc0); acc1 = fmaf(p3, v3.y, acc1);
    }
    for (; j < end; j++) {
        int src = g_csr[j];
        float p = __expf(lrelu(g_as1[src * H1 + h] + adh));
        sum_p += p;
        float2 v = *(const float2*)(g_h1 + (long)src * HC + 2 * lane);
        acc0 = fmaf(p, v.x, acc0);
        acc1 = fmaf(p, v.y, acc1);
    }
    float inv = 1.0f / (sum_p + 1e-16f);
    float o0 = acc0 * inv + b1[2 * lane];
    float o1 = acc1 * inv + b1[2 * lane + 1];
    o0 = o0 > 0.f ? o0 : (expf(o0) - 1.f);
    o1 = o1 > 0.f ? o1 : (expf(o1) - 1.f);
    *(float2*)(g_o1 + (long)n * HC + 2 * lane) = make_float2(o0, o1);
}

// ---------------- GEMM2 + fused alpha2 ----------------
__global__ void k_gemm2(const float* __restrict__ W2,
                        const float* __restrict__ a_s, const float* __restrict__ a_d) {
    __shared__ float Ws[HC * NC];
    __shared__ float rows[32 * HC];
    __shared__ float zsm[32 * 41];
    const int t = threadIdx.x;
    const int base = blockIdx.x * 32;
    for (int i = t; i < HC * NC; i += 256) Ws[i] = W2[i];
    for (int i = t; i < 32 * HC; i += 256) {
        int r = i / HC, k = i % HC;
        int gn = base + r;
        rows[i] = (gn < NN) ? g_o1[(long)gn * HC + k] : 0.0f;
    }
    __syncthreads();
    for (int o = t; o < 32 * NC; o += 256) {
        int r = o / NC, c = o % NC;
        int gn = base + r;
        float acc = 0.f;
        const float* rp = rows + r * HC;
        #pragma unroll
        for (int k = 0; k < HC; k++) acc = fmaf(rp[k], Ws[k * NC + c], acc);
        zsm[r * 41 + c] = acc;
        if (gn < NN) g_z[(long)gn * NC + c] = acc;
    }
    __syncthreads();
    if (t < 32) {
        int gn = base + t;
        if (gn < NN) {
            float s = 0.f, d = 0.f;
            #pragma unroll
            for (int c = 0; c < NC; c++) {
                float v = zsm[t * 41 + c];
                s = fmaf(v, a_s[c], s);
                d = fmaf(v, a_d[c], d);
            }
            g_as2[gn] = s;
            g_ad2[gn] = d;
        }
    }
}

// ---------------- layer-2 CSR aggregation + log_softmax (unroll x4) ----------------
__global__ void k_agg2(float* __restrict__ out, const float* __restrict__ b2) {
    int warp = (blockIdx.x * blockDim.x + threadIdx.x) >> 5;
    if (warp >= NN) return;
    int lane = threadIdx.x & 31;
    int n = warp;
    float ad = g_ad2[n];
    int beg = g_row[n], end = g_row[n + 1];
    float sp = 0.f, acc_a = 0.f, acc_b = 0.f;
    int j = beg;
    for (; j + 4 <= end; j += 4) {
        int s0 = g_csr[j], s1 = g_csr[j + 1], s2 = g_csr[j + 2], s3 = g_csr[j + 3];
        float e0 = g_as2[s0], e1 = g_as2[s1], e2 = g_as2[s2], e3 = g_as2[s3];
        const float* z0 = g_z + (long)s0 * NC;
        const float* z1 = g_z + (long)s1 * NC;
        const float* z2 = g_z + (long)s2 * NC;
        const float* z3 = g_z + (long)s3 * NC;
        float w0 = z0[lane], w1 = z1[lane], w2 = z2[lane], w3 = z3[lane];
        float u0 = 0.f, u1 = 0.f, u2 = 0.f, u3 = 0.f;
        if (lane < 8) { u0 = z0[32 + lane]; u1 = z1[32 + lane]; u2 = z2[32 + lane]; u3 = z3[32 + lane]; }
        float p0 = __expf(lrelu(e0 + ad));
        float p1 = __expf(lrelu(e1 + ad));
        float p2 = __expf(lrelu(e2 + ad));
        float p3 = __expf(lrelu(e3 + ad));
        sp += (p0 + p1) + (p2 + p3);
        acc_a = fmaf(p0, w0, acc_a); acc_b = fmaf(p0, u0, acc_b);
        acc_a = fmaf(p1, w1, acc_a); acc_b = fmaf(p1, u1, acc_b);
        acc_a = fmaf(p2, w2, acc_a); acc_b = fmaf(p2, u2, acc_b);
        acc_a = fmaf(p3, w3, acc_a); acc_b = fmaf(p3, u3, acc_b);
    }
    for (; j < end; j++) {
        int src = g_csr[j];
        float p = __expf(lrelu(g_as2[src] + ad));
        sp += p;
        const float* zp = g_z + (long)src * NC;
        acc_a = fmaf(p, zp[lane], acc_a);
        if (lane < 8) acc_b = fmaf(p, zp[32 + lane], acc_b);
    }
    float inv = 1.0f / (sp + 1e-16f);
    float va = acc_a * inv + b2[lane];
    float vb = (lane < 8) ? acc_b * inv + b2[32 + lane] : -3.402823466e38f;
    float m = fmaxf(va, vb);
    #pragma unroll
    for (int off = 16; off > 0; off >>= 1)
        m = fmaxf(m, __shfl_xor_sync(0xffffffffu, m, off));
    float s = expf(va - m) + ((lane < 8) ? expf(vb - m) : 0.f);
    #pragma unroll
    for (int off = 16; off > 0; off >>= 1)
        s += __shfl_xor_sync(0xffffffffu, s, off);
    float lse = m + logf(s);
    float* op = out + (long)n * NC;
    op[lane] = va - lse;
    if (lane < 8) op[32 + lane] = vb - lse;
}

// ---------------- launch ----------------
extern "C" void kernel_launch(void* const* d_in, const int* in_sizes, int n_in,
                              void* d_out, int out_size) {
    const float* x    = (const float*)d_in[0];
    const void*  ei   = d_in[1];
    const float* W1   = (const float*)d_in[2];
    const float* as1  = (const float*)d_in[3];
    const float* ad1  = (const float*)d_in[4];
    const float* b1   = (const float*)d_in[5];
    const float* W2   = (const float*)d_in[6];
    const float* as2  = (const float*)d_in[7];
    const float* ad2  = (const float*)d_in[8];
    const float* b2   = (const float*)d_in[9];
    float*       out  = (float*)d_out;

    const int TB = 256;
    k_init   <<<(NN + TB - 1) / TB, TB>>>();
    k_detect <<<8, 256>>>(ei);
    k_convert<<<(ETOT + TB - 1) / TB, TB>>>(ei);
    k_prepW  <<<(FIN * HC + TB - 1) / TB, TB>>>(W1);
    k_scan1  <<<NBLK, 1024>>>();
    k_scan2  <<<1, 32>>>();
    k_scan3  <<<(NN + TB - 1) / TB, TB>>>();
    k_scatter<<<(ETOT + TB - 1) / TB, TB>>>();
    k_gemm1  <<<(NN + 127) / 128, 256>>>(x);
    k_alpha1 <<<(NN * H1 + TB - 1) / TB, TB>>>(as1, ad1);
    k_agg1   <<<(NN * 32 + TB - 1) / TB, TB>>>(b1);
    k_gemm2  <<<(NN + 31) / 32, 256>>>(W2, as2, ad2);
    k_agg2   <<<(NN * 32 + TB - 1) / TB, TB>>>(out, b2);
}

// round 6
// speedup vs baseline: 1.0286x; 1.0286x over previous
#include <cuda_runtime.h>
#include <cuda_bf16.h>
#include <math.h>

#define NN 100000
#define EE 1600000
#define FIN 512
#define H1 8
#define C1 8
#define HC 64
#define NC 40
#define ETOT (EE + NN)
#define NEG_SLOPE 0.2f
#define NBLK 98   // ceil(NN/1024)

// ---------------- scratch ----------------
__device__ float g_h1[NN * HC];
__device__ float g_as1[NN * H1];
__device__ float g_ad1[NN * H1];
__device__ float g_o1[NN * HC];
__device__ float g_z[NN * NC];
__device__ float g_as2[NN];
__device__ float g_ad2[NN];
__device__ int   g_src[ETOT];
__device__ int   g_dst[ETOT];
__device__ int   g_deg[NN];
__device__ int   g_row[NN + 1];
__device__ int   g_cursor[NN];
__device__ int   g_bsum[NBLK];
__device__ int   g_csr[ETOT];
// monotone flag: only ever AND-ed to 0; converges to the same value every call
__device__ int   g_is64 = 1;
__device__ unsigned short g_W1T_hi[HC * FIN];
__device__ unsigned short g_W1T_lo[HC * FIN];

__device__ __forceinline__ float lrelu(float x) {
    return x > 0.0f ? x : NEG_SLOPE * x;
}

__device__ __forceinline__ void split_bf16(float v, unsigned short& hi, unsigned short& lo) {
    __nv_bfloat16 h = __float2bfloat16(v);
    float r = v - __bfloat162float(h);
    __nv_bfloat16 l = __float2bfloat16(r);
    hi = __bfloat16_as_ushort(h);
    lo = __bfloat16_as_ushort(l);
}

__device__ __forceinline__ void mma_bf16(float* c, const unsigned* a, const unsigned* b) {
    asm volatile(
        "mma.sync.aligned.m16n8k16.row.col.f32.bf16.bf16.f32 "
        "{%0,%1,%2,%3},{%4,%5,%6,%7},{%8,%9},{%0,%1,%2,%3};"
        : "+f"(c[0]), "+f"(c[1]), "+f"(c[2]), "+f"(c[3])
        : "r"(a[0]), "r"(a[1]), "r"(a[2]), "r"(a[3]), "r"(b[0]), "r"(b[1]));
}

// ---------------- init + dtype probe ----------------
__global__ void k_init(const void* __restrict__ ei) {
    int i = blockIdx.x * blockDim.x + threadIdx.x;
    if (i < NN) g_deg[i] = 0;
    if (i < 2048) {
        long long v = ((const long long*)ei)[i];
        if (v < 0 || v >= NN) atomicAnd(&g_is64, 0);
    }
}

// ---------------- edge conversion + degree count ----------------
__global__ void k_convert(const void* __restrict__ ei) {
    int idx = blockIdx.x * blockDim.x + threadIdx.x;
    if (idx >= ETOT) return;
    int s, d;
    if (idx < EE) {
        if (g_is64) {
            const long long* p = (const long long*)ei;
            s = (int)p[idx];
            d = (int)p[EE + idx];
        } else {
            const int* p = (const int*)ei;
            s = p[idx];
            d = p[EE + idx];
        }
    } else {
        s = d = idx - EE;
    }
    s = min(max(s, 0), NN - 1);
    d = min(max(d, 0), NN - 1);
    g_src[idx] = s;
    g_dst[idx] = d;
    atomicAdd(&g_deg[d], 1);
}

// ---------------- exclusive scan of degrees ----------------
__global__ void k_scan1() {
    __shared__ int sh[1024];
    int tid = threadIdx.x;
    int i = blockIdx.x * 1024 + tid;
    int v = (i < NN) ? g_deg[i] : 0;
    sh[tid] = v;
    __syncthreads();
    #pragma unroll
    for (int off = 1; off < 1024; off <<= 1) {
        int t = (tid >= off) ? sh[tid - off] : 0;
        __syncthreads();
        sh[tid] += t;
        __syncthreads();
    }
    if (i < NN) g_row[i] = sh[tid] - v;
    if (tid == 1023) g_bsum[blockIdx.x] = sh[1023];
}

__global__ void k_scan2() {
    if (threadIdx.x == 0) {
        int acc = 0;
        for (int b = 0; b < NBLK; b++) { int t = g_bsum[b]; g_bsum[b] = acc; acc += t; }
        g_row[NN] = acc;
    }
}

__global__ void k_scan3() {
    int i = blockIdx.x * blockDim.x + threadIdx.x;
    if (i < NN) {
        int r = g_row[i] + g_bsum[i >> 10];
        g_row[i] = r;
        g_cursor[i] = r;
    }
}

__global__ void k_scatter() {
    int idx = blockIdx.x * blockDim.x + threadIdx.x;
    if (idx >= ETOT) return;
    int d = g_dst[idx];
    int pos = atomicAdd(&g_cursor[d], 1);
    g_csr[pos] = g_src[idx];
}

// ---------------- W1 split/transpose ----------------
__global__ void k_prepW(const float* __restrict__ W1) {
    int i = blockIdx.x * blockDim.x + threadIdx.x;
    if (i >= FIN * HC) return;
    int k = i / HC, n = i % HC;
    unsigned short hi, lo;
    split_bf16(W1[i], hi, lo);
    g_W1T_hi[n * FIN + k] = hi;
    g_W1T_lo[n * FIN + k] = lo;
}

// ---------------- GEMM1 (bf16x3 tensor cores) + fused alpha1 epilogue ----------------
#define ASTR 40
__global__ __launch_bounds__(256) void k_gemm1(const float* __restrict__ x,
                                               const float* __restrict__ a_s,
                                               const float* __restrict__ a_d) {
    __shared__ unsigned short As_hi[128 * ASTR];
    __shared__ unsigned short As_lo[128 * ASTR];
    __shared__ unsigned short Bs_hi[64 * ASTR];
    __shared__ unsigned short Bs_lo[64 * ASTR];

    const int t = threadIdx.x;
    const int bm0 = blockIdx.x * 128;
    const int warp = t >> 5;
    const int lane = t & 31;
    const int g = lane >> 2;
    const int q = lane & 3;
    const int warp_m = warp >> 1;
    const int warp_n = warp & 1;

    float acc[2][4][4];
    #pragma unroll
    for (int i = 0; i < 2; i++)
        #pragma unroll
        for (int j = 0; j < 4; j++)
            #pragma unroll
            for (int r = 0; r < 4; r++) acc[i][j][r] = 0.f;

    for (int k0 = 0; k0 < FIN; k0 += 32) {
        #pragma unroll
        for (int i = 0; i < 4; i++) {
            int idx = i * 256 + t;
            int row = idx >> 3;
            int col = (idx & 7) * 4;
            float4 v = make_float4(0.f, 0.f, 0.f, 0.f);
            int gr = bm0 + row;
            if (gr < NN) v = *(const float4*)(x + (long)gr * FIN + k0 + col);
            unsigned short h0, l0, h1_, l1_, h2, l2, h3, l3;
            split_bf16(v.x, h0, l0);
            split_bf16(v.y, h1_, l1_);
            split_bf16(v.z, h2, l2);
            split_bf16(v.w, h3, l3);
            unsigned* ph = (unsigned*)&As_hi[row * ASTR + col];
            unsigned* pl = (unsigned*)&As_lo[row * ASTR + col];
            ph[0] = (unsigned)h0 | ((unsigned)h1_ << 16);
            ph[1] = (unsigned)h2 | ((unsigned)h3 << 16);
            pl[0] = (unsigned)l0 | ((unsigned)l1_ << 16);
            pl[1] = (unsigned)l2 | ((unsigned)l3 << 16);
        }
        {
            int row = t >> 2;
            int seg = t & 3;
            uint4 vh = *(const uint4*)&g_W1T_hi[row * FIN + k0 + seg * 8];
            uint4 vl = *(const uint4*)&g_W1T_lo[row * FIN + k0 + seg * 8];
            *(uint4*)&Bs_hi[row * ASTR + seg * 8] = vh;
            *(uint4*)&Bs_lo[row * ASTR + seg * 8] = vl;
        }
        __syncthreads();

        #pragma unroll
        for (int ka = 0; ka < 2; ka++) {
            const int kc = ka * 16;
            unsigned a_hi[2][4], a_lo[2][4], b_hi[4][2], b_lo[4][2];
            #pragma unroll
            for (int ma = 0; ma < 2; ma++) {
                int r0 = warp_m * 32 + ma * 16;
                a_hi[ma][0] = *(const unsigned*)&As_hi[(r0 + g) * ASTR + kc + 2 * q];
                a_hi[ma][1] = *(const unsigned*)&As_hi[(r0 + g + 8) * ASTR + kc + 2 * q];
                a_hi[ma][2] = *(const unsigned*)&As_hi[(r0 + g) * ASTR + kc + 2 * q + 8];
                a_hi[ma][3] = *(const unsigned*)&As_hi[(r0 + g + 8) * ASTR + kc + 2 * q + 8];
                a_lo[ma][0] = *(const unsigned*)&As_lo[(r0 + g) * ASTR + kc + 2 * q];
                a_lo[ma][1] = *(const unsigned*)&As_lo[(r0 + g + 8) * ASTR + kc + 2 * q];
                a_lo[ma][2] = *(const unsigned*)&As_lo[(r0 + g) * ASTR + kc + 2 * q + 8];
                a_lo[ma][3] = *(const unsigned*)&As_lo[(r0 + g + 8) * ASTR + kc + 2 * q + 8];
            }
            #pragma unroll
            for (int na = 0; na < 4; na++) {
                int n0 = warp_n * 32 + na * 8;
                b_hi[na][0] = *(const unsigned*)&Bs_hi[(n0 + g) * ASTR + kc + 2 * q];
                b_hi[na][1] = *(const unsigned*)&Bs_hi[(n0 + g) * ASTR + kc + 2 * q + 8];
                b_lo[na][0] = *(const unsigned*)&Bs_lo[(n0 + g) * ASTR + kc + 2 * q];
                b_lo[na][1] = *(const unsigned*)&Bs_lo[(n0 + g) * ASTR + kc + 2 * q + 8];
            }
            #pragma unroll
            for (int ma = 0; ma < 2; ma++)
                #pragma unroll
                for (int na = 0; na < 4; na++) {
                    mma_bf16(acc[ma][na], a_hi[ma], b_hi[na]);
                    mma_bf16(acc[ma][na], a_hi[ma], b_lo[na]);
                    mma_bf16(acc[ma][na], a_lo[ma], b_hi[na]);
                }
        }
        __syncthreads();
    }

    // ---- epilogue: write h1 ----
    #pragma unroll
    for (int ma = 0; ma < 2; ma++) {
        int r0 = bm0 + warp_m * 32 + ma * 16 + g;
        #pragma unroll
        for (int na = 0; na < 4; na++) {
            int c = warp_n * 32 + na * 8 + 2 * q;
            if (r0 < NN)
                *(float2*)(g_h1 + (long)r0 * HC + c) = make_float2(acc[ma][na][0], acc[ma][na][1]);
            if (r0 + 8 < NN)
                *(float2*)(g_h1 + (long)(r0 + 8) * HC + c) = make_float2(acc[ma][na][2], acc[ma][na][3]);
        }
    }

    // ---- fused alpha1: per na, acc covers one head's channels 2q,2q+1 ----
    float as_c0[4], as_c1[4], ad_c0[4], ad_c1[4];
    #pragma unroll
    for (int na = 0; na < 4; na++) {
        int hh = warp_n * 4 + na;
        as_c0[na] = a_s[hh * 8 + 2 * q];
        as_c1[na] = a_s[hh * 8 + 2 * q + 1];
        ad_c0[na] = a_d[hh * 8 + 2 * q];
        ad_c1[na] = a_d[hh * 8 + 2 * q + 1];
    }
    #pragma unroll
    for (int ma = 0; ma < 2; ma++)
        #pragma unroll
        for (int rh = 0; rh < 2; rh++) {
            float s[4], d[4];
            #pragma unroll
            for (int na = 0; na < 4; na++) {
                float h0 = acc[ma][na][rh * 2 + 0];
                float h1v = acc[ma][na][rh * 2 + 1];
                s[na] = h0 * as_c0[na] + h1v * as_c1[na];
                d[na] = h0 * ad_c0[na] + h1v * ad_c1[na];
            }
            #pragma unroll
            for (int na = 0; na < 4; na++) {
                s[na] += __shfl_xor_sync(0xffffffffu, s[na], 1);
                s[na] += __shfl_xor_sync(0xffffffffu, s[na], 2);
                d[na] += __shfl_xor_sync(0xffffffffu, d[na], 1);
                d[na] += __shfl_xor_sync(0xffffffffu, d[na], 2);
            }
            int row = bm0 + warp_m * 32 + ma * 16 + rh * 8 + g;
            if (q == 0 && row < NN) {
                *(float4*)(g_as1 + row * H1 + warp_n * 4) = make_float4(s[0], s[1], s[2], s[3]);
                *(float4*)(g_ad1 + row * H1 + warp_n * 4) = make_float4(d[0], d[1], d[2], d[3]);
            }
        }
}

// ---------------- layer-1 CSR aggregation: half-warp per edge, float4 gathers ----------------
__global__ void k_agg1(const float* __restrict__ b1) {
    int warp = (blockIdx.x * blockDim.x + threadIdx.x) >> 5;
    if (warp >= NN) return;
    int lane = threadIdx.x & 31;
    int half = lane >> 4;          // 0 or 1: which edge of the pair
    int l = lane & 15;             // position within half-warp
    int c = l * 4;                 // channel base (0..60)
    int h = l >> 1;                // head = c/8
    int n = warp;
    float adh = g_ad1[n * H1 + h];
    int beg = g_row[n], end = g_row[n + 1];
    float sum_p = 0.f, a0 = 0.f, a1 = 0.f, a2 = 0.f, a3 = 0.f;

    int j = beg + half;
    for (; j + 2 < end; j += 4) {   // edges j and j+2 for this half
        int s0 = g_csr[j], s1 = g_csr[j + 2];
        float e0 = g_as1[s0 * H1 + h];
        float e1 = g_as1[s1 * H1 + h];
        float4 v0 = *(const float4*)(g_h1 + (long)s0 * HC + c);
        float4 v1 = *(const float4*)(g_h1 + (long)s1 * HC + c);
        float p0 = __expf(lrelu(e0 + adh));
        float p1 = __expf(lrelu(e1 + adh));
        sum_p += p0 + p1;
        a0 = fmaf(p0, v0.x, a0); a1 = fmaf(p0, v0.y, a1);
        a2 = fmaf(p0, v0.z, a2); a3 = fmaf(p0, v0.w, a3);
        a0 = fmaf(p1, v1.x, a0); a1 = fmaf(p1, v1.y, a1);
        a2 = fmaf(p1, v1.z, a2); a3 = fmaf(p1, v1.w, a3);
    }
    for (; j < end; j += 2) {
        int s0 = g_csr[j];
        float e0 = g_as1[s0 * H1 + h];
        float4 v0 = *(const float4*)(g_h1 + (long)s0 * HC + c);
        float p0 = __expf(lrelu(e0 + adh));
        sum_p += p0;
        a0 = fmaf(p0, v0.x, a0); a1 = fmaf(p0, v0.y, a1);
        a2 = fmaf(p0, v0.z, a2); a3 = fmaf(p0, v0.w, a3);
    }
    // combine the two halves
    a0 += __shfl_xor_sync(0xffffffffu, a0, 16);
    a1 += __shfl_xor_sync(0xffffffffu, a1, 16);
    a2 += __shfl_xor_sync(0xffffffffu, a2, 16);
    a3 += __shfl_xor_sync(0xffffffffu, a3, 16);
    sum_p += __shfl_xor_sync(0xffffffffu, sum_p, 16);

    if (half == 0) {
        float inv = 1.0f / (sum_p + 1e-16f);
        float4 bb = *(const float4*)(b1 + c);
        float o0 = a0 * inv + bb.x;
        float o1 = a1 * inv + bb.y;
        float o2 = a2 * inv + bb.z;
        float o3 = a3 * inv + bb.w;
        o0 = o0 > 0.f ? o0 : (expf(o0) - 1.f);
        o1 = o1 > 0.f ? o1 : (expf(o1) - 1.f);
        o2 = o2 > 0.f ? o2 : (expf(o2) - 1.f);
        o3 = o3 > 0.f ? o3 : (expf(o3) - 1.f);
        *(float4*)(g_o1 + (long)n * HC + c) = make_float4(o0, o1, o2, o3);
    }
}

// ---------------- GEMM2 + fused alpha2 ----------------
__global__ void k_gemm2(const float* __restrict__ W2,
                        const float* __restrict__ a_s, const float* __restrict__ a_d) {
    __shared__ float Ws[HC * NC];
    __shared__ float rows[32 * HC];
    __shared__ float zsm[32 * 41];
    const int t = threadIdx.x;
    const int base = blockIdx.x * 32;
    for (int i = t; i < HC * NC; i += 256) Ws[i] = W2[i];
    for (int i = t; i < 32 * HC; i += 256) {
        int r = i / HC, k = i % HC;
        int gn = base + r;
        rows[i] = (gn < NN) ? g_o1[(long)gn * HC + k] : 0.0f;
    }
    __syncthreads();
    for (int o = t; o < 32 * NC; o += 256) {
        int r = o / NC, c = o % NC;
        int gn = base + r;
        float acc = 0.f;
        const float* rp = rows + r * HC;
        #pragma unroll
        for (int k = 0; k < HC; k++) acc = fmaf(rp[k], Ws[k * NC + c], acc);
        zsm[r * 41 + c] = acc;
        if (gn < NN) g_z[(long)gn * NC + c] = acc;
    }
    __syncthreads();
    if (t < 32) {
        int gn = base + t;
        if (gn < NN) {
            float s = 0.f, d = 0.f;
            #pragma unroll
            for (int c = 0; c < NC; c++) {
                float v = zsm[t * 41 + c];
                s = fmaf(v, a_s[c], s);
                d = fmaf(v, a_d[c], d);
            }
            g_as2[gn] = s;
            g_ad2[gn] = d;
        }
    }
}

// ---------------- layer-2 CSR aggregation + log_softmax (unroll x4) ----------------
__global__ void k_agg2(float* __restrict__ out, const float* __restrict__ b2) {
    int warp = (blockIdx.x * blockDim.x + threadIdx.x) >> 5;
    if (warp >= NN) return;
    int lane = threadIdx.x & 31;
    int n = warp;
    float ad = g_ad2[n];
    int beg = g_row[n], end = g_row[n + 1];
    float sp = 0.f, acc_a = 0.f, acc_b = 0.f;
    int j = beg;
    for (; j + 4 <= end; j += 4) {
        int s0 = g_csr[j], s1 = g_csr[j + 1], s2 = g_csr[j + 2], s3 = g_csr[j + 3];
        float e0 = g_as2[s0], e1 = g_as2[s1], e2 = g_as2[s2], e3 = g_as2[s3];
        const float* z0 = g_z + (long)s0 * NC;
        const float* z1 = g_z + (long)s1 * NC;
        const float* z2 = g_z + (long)s2 * NC;
        const float* z3 = g_z + (long)s3 * NC;
        float w0 = z0[lane], w1 = z1[lane], w2 = z2[lane], w3 = z3[lane];
        float u0 = 0.f, u1 = 0.f, u2 = 0.f, u3 = 0.f;
        if (lane < 8) { u0 = z0[32 + lane]; u1 = z1[32 + lane]; u2 = z2[32 + lane]; u3 = z3[32 + lane]; }
        float p0 = __expf(lrelu(e0 + ad));
        float p1 = __expf(lrelu(e1 + ad));
        float p2 = __expf(lrelu(e2 + ad));
        float p3 = __expf(lrelu(e3 + ad));
        sp += (p0 + p1) + (p2 + p3);
        acc_a = fmaf(p0, w0, acc_a); acc_b = fmaf(p0, u0, acc_b);
        acc_a = fmaf(p1, w1, acc_a); acc_b = fmaf(p1, u1, acc_b);
        acc_a = fmaf(p2, w2, acc_a); acc_b = fmaf(p2, u2, acc_b);
        acc_a = fmaf(p3, w3, acc_a); acc_b = fmaf(p3, u3, acc_b);
    }
    for (; j < end; j++) {
        int src = g_csr[j];
        float p = __expf(lrelu(g_as2[src] + ad));
        sp += p;
        const float* zp = g_z + (long)src * NC;
        acc_a = fmaf(p, zp[lane], acc_a);
        if (lane < 8) acc_b = fmaf(p, zp[32 + lane], acc_b);
    }
    float inv = 1.0f / (sp + 1e-16f);
    float va = acc_a * inv + b2[lane];
    float vb = (lane < 8) ? acc_b * inv + b2[32 + lane] : -3.402823466e38f;
    float m = fmaxf(va, vb);
    #pragma unroll
    for (int off = 16; off > 0; off >>= 1)
        m = fmaxf(m, __shfl_xor_sync(0xffffffffu, m, off));
    float s = expf(va - m) + ((lane < 8) ? expf(vb - m) : 0.f);
    #pragma unroll
    for (int off = 16; off > 0; off >>= 1)
        s += __shfl_xor_sync(0xffffffffu, s, off);
    float lse = m + logf(s);
    float* op = out + (long)n * NC;
    op[lane] = va - lse;
    if (lane < 8) op[32 + lane] = vb - lse;
}

// ---------------- launch ----------------
extern "C" void kernel_launch(void* const* d_in, const int* in_sizes, int n_in,
                              void* d_out, int out_size) {
    const float* x    = (const float*)d_in[0];
    const void*  ei   = d_in[1];
    const float* W1   = (const float*)d_in[2];
    const float* as1  = (const float*)d_in[3];
    const float* ad1  = (const float*)d_in[4];
    const float* b1   = (const float*)d_in[5];
    const float* W2   = (const float*)d_in[6];
    const float* as2  = (const float*)d_in[7];
    const float* ad2  = (const float*)d_in[8];
    const float* b2   = (const float*)d_in[9];
    float*       out  = (float*)d_out;

    const int TB = 256;
    k_init   <<<(NN + TB - 1) / TB, TB>>>(ei);
    k_convert<<<(ETOT + TB - 1) / TB, TB>>>(ei);
    k_prepW  <<<(FIN * HC + TB - 1) / TB, TB>>>(W1);
    k_scan1  <<<NBLK, 1024>>>();
    k_scan2  <<<1, 32>>>();
    k_scan3  <<<(NN + TB - 1) / TB, TB>>>();
    k_scatter<<<(ETOT + TB - 1) / TB, TB>>>();
    k_gemm1  <<<(NN + 127) / 128, 256>>>(x, as1, ad1);
    k_agg1   <<<(NN * 32 + TB - 1) / TB, TB>>>(b1);
    k_gemm2  <<<(NN + 31) / 32, 256>>>(W2, as2, ad2);
    k_agg2   <<<(NN * 32 + TB - 1) / TB, TB>>>(out, b2);
}

// round 7
// speedup vs baseline: 1.1253x; 1.0941x over previous
#include <cuda_runtime.h>
#include <cuda_bf16.h>
#include <math.h>

#define NN 100000
#define EE 1600000
#define FIN 512
#define H1 8
#define C1 8
#define HC 64
#define NC 40
#define ETOT (EE + NN)
#define NEG_SLOPE 0.2f
#define NBLK 98   // ceil(NN/1024)

// ---------------- scratch ----------------
__device__ float g_h1[NN * HC];
__device__ float g_as1[NN * H1];
__device__ float g_ad1[NN * H1];
__device__ float g_o1[NN * HC];
__device__ float g_z[NN * NC];
__device__ float g_as2[NN];
__device__ float g_ad2[NN];
__device__ int   g_src[ETOT];
__device__ int   g_dst[ETOT];
__device__ int   g_deg[NN];
__device__ int   g_row[NN + 1];
__device__ int   g_cursor[NN];
__device__ int   g_bsum[NBLK];
__device__ int   g_csr[ETOT];
// monotone flag: only ever AND-ed to 0; converges to the same value every call
__device__ int   g_is64 = 1;
__device__ unsigned short g_W1T_hi[HC * FIN];
__device__ unsigned short g_W1T_lo[HC * FIN];

__device__ __forceinline__ float lrelu(float x) {
    return x > 0.0f ? x : NEG_SLOPE * x;
}

__device__ __forceinline__ void split_bf16(float v, unsigned short& hi, unsigned short& lo) {
    __nv_bfloat16 h = __float2bfloat16(v);
    float r = v - __bfloat162float(h);
    __nv_bfloat16 l = __float2bfloat16(r);
    hi = __bfloat16_as_ushort(h);
    lo = __bfloat16_as_ushort(l);
}

__device__ __forceinline__ void mma_bf16(float* c, const unsigned* a, const unsigned* b) {
    asm volatile(
        "mma.sync.aligned.m16n8k16.row.col.f32.bf16.bf16.f32 "
        "{%0,%1,%2,%3},{%4,%5,%6,%7},{%8,%9},{%0,%1,%2,%3};"
        : "+f"(c[0]), "+f"(c[1]), "+f"(c[2]), "+f"(c[3])
        : "r"(a[0]), "r"(a[1]), "r"(a[2]), "r"(a[3]), "r"(b[0]), "r"(b[1]));
}

// ---------------- init + dtype probe ----------------
__global__ void k_init(const void* __restrict__ ei) {
    int i = blockIdx.x * blockDim.x + threadIdx.x;
    if (i < NN) g_deg[i] = 0;
    if (i < 2048) {
        long long v = ((const long long*)ei)[i];
        if (v < 0 || v >= NN) atomicAnd(&g_is64, 0);
    }
}

// ---------------- edge conversion + degree count ----------------
__global__ void k_convert(const void* __restrict__ ei) {
    int idx = blockIdx.x * blockDim.x + threadIdx.x;
    if (idx >= ETOT) return;
    int s, d;
    if (idx < EE) {
        if (g_is64) {
            const long long* p = (const long long*)ei;
            s = (int)p[idx];
            d = (int)p[EE + idx];
        } else {
            const int* p = (const int*)ei;
            s = p[idx];
            d = p[EE + idx];
        }
    } else {
        s = d = idx - EE;
    }
    s = min(max(s, 0), NN - 1);
    d = min(max(d, 0), NN - 1);
    g_src[idx] = s;
    g_dst[idx] = d;
    atomicAdd(&g_deg[d], 1);
}

// ---------------- exclusive scan of degrees ----------------
__global__ void k_scan1() {
    __shared__ int sh[1024];
    int tid = threadIdx.x;
    int i = blockIdx.x * 1024 + tid;
    int v = (i < NN) ? g_deg[i] : 0;
    sh[tid] = v;
    __syncthreads();
    #pragma unroll
    for (int off = 1; off < 1024; off <<= 1) {
        int t = (tid >= off) ? sh[tid - off] : 0;
        __syncthreads();
        sh[tid] += t;
        __syncthreads();
    }
    if (i < NN) g_row[i] = sh[tid] - v;
    if (tid == 1023) g_bsum[blockIdx.x] = sh[1023];
}

__global__ void k_scan2() {
    if (threadIdx.x == 0) {
        int acc = 0;
        for (int b = 0; b < NBLK; b++) { int t = g_bsum[b]; g_bsum[b] = acc; acc += t; }
        g_row[NN] = acc;
    }
}

__global__ void k_scan3() {
    int i = blockIdx.x * blockDim.x + threadIdx.x;
    if (i < NN) {
        int r = g_row[i] + g_bsum[i >> 10];
        g_row[i] = r;
        g_cursor[i] = r;
    }
}

__global__ void k_scatter() {
    int idx = blockIdx.x * blockDim.x + threadIdx.x;
    if (idx >= ETOT) return;
    int d = g_dst[idx];
    int pos = atomicAdd(&g_cursor[d], 1);
    g_csr[pos] = g_src[idx];
}

// ---------------- W1 split/transpose ----------------
__global__ void k_prepW(const float* __restrict__ W1) {
    int i = blockIdx.x * blockDim.x + threadIdx.x;
    if (i >= FIN * HC) return;
    int k = i / HC, n = i % HC;
    unsigned short hi, lo;
    split_bf16(W1[i], hi, lo);
    g_W1T_hi[n * FIN + k] = hi;
    g_W1T_lo[n * FIN + k] = lo;
}

// ---------------- GEMM1 (bf16x3 tensor cores) + fused alpha1 epilogue ----------------
#define ASTR 40
__global__ __launch_bounds__(256) void k_gemm1(const float* __restrict__ x,
                                               const float* __restrict__ a_s,
                                               const float* __restrict__ a_d) {
    __shared__ unsigned short As_hi[128 * ASTR];
    __shared__ unsigned short As_lo[128 * ASTR];
    __shared__ unsigned short Bs_hi[64 * ASTR];
    __shared__ unsigned short Bs_lo[64 * ASTR];

    const int t = threadIdx.x;
    const int bm0 = blockIdx.x * 128;
    const int warp = t >> 5;
    const int lane = t & 31;
    const int g = lane >> 2;
    const int q = lane & 3;
    const int warp_m = warp >> 1;
    const int warp_n = warp & 1;

    float acc[2][4][4];
    #pragma unroll
    for (int i = 0; i < 2; i++)
        #pragma unroll
        for (int j = 0; j < 4; j++)
            #pragma unroll
            for (int r = 0; r < 4; r++) acc[i][j][r] = 0.f;

    for (int k0 = 0; k0 < FIN; k0 += 32) {
        #pragma unroll
        for (int i = 0; i < 4; i++) {
            int idx = i * 256 + t;
            int row = idx >> 3;
            int col = (idx & 7) * 4;
            float4 v = make_float4(0.f, 0.f, 0.f, 0.f);
            int gr = bm0 + row;
            if (gr < NN) v = *(const float4*)(x + (long)gr * FIN + k0 + col);
            unsigned short h0, l0, h1_, l1_, h2, l2, h3, l3;
            split_bf16(v.x, h0, l0);
            split_bf16(v.y, h1_, l1_);
            split_bf16(v.z, h2, l2);
            split_bf16(v.w, h3, l3);
            unsigned* ph = (unsigned*)&As_hi[row * ASTR + col];
            unsigned* pl = (unsigned*)&As_lo[row * ASTR + col];
            ph[0] = (unsigned)h0 | ((unsigned)h1_ << 16);
            ph[1] = (unsigned)h2 | ((unsigned)h3 << 16);
            pl[0] = (unsigned)l0 | ((unsigned)l1_ << 16);
            pl[1] = (unsigned)l2 | ((unsigned)l3 << 16);
        }
        {
            int row = t >> 2;
            int seg = t & 3;
            uint4 vh = *(const uint4*)&g_W1T_hi[row * FIN + k0 + seg * 8];
            uint4 vl = *(const uint4*)&g_W1T_lo[row * FIN + k0 + seg * 8];
            *(uint4*)&Bs_hi[row * ASTR + seg * 8] = vh;
            *(uint4*)&Bs_lo[row * ASTR + seg * 8] = vl;
        }
        __syncthreads();

        #pragma unroll
        for (int ka = 0; ka < 2; ka++) {
            const int kc = ka * 16;
            unsigned a_hi[2][4], a_lo[2][4], b_hi[4][2], b_lo[4][2];
            #pragma unroll
            for (int ma = 0; ma < 2; ma++) {
                int r0 = warp_m * 32 + ma * 16;
                a_hi[ma][0] = *(const unsigned*)&As_hi[(r0 + g) * ASTR + kc + 2 * q];
                a_hi[ma][1] = *(const unsigned*)&As_hi[(r0 + g + 8) * ASTR + kc + 2 * q];
                a_hi[ma][2] = *(const unsigned*)&As_hi[(r0 + g) * ASTR + kc + 2 * q + 8];
                a_hi[ma][3] = *(const unsigned*)&As_hi[(r0 + g + 8) * ASTR + kc + 2 * q + 8];
                a_lo[ma][0] = *(const unsigned*)&As_lo[(r0 + g) * ASTR + kc + 2 * q];
                a_lo[ma][1] = *(const unsigned*)&As_lo[(r0 + g + 8) * ASTR + kc + 2 * q];
                a_lo[ma][2] = *(const unsigned*)&As_lo[(r0 + g) * ASTR + kc + 2 * q + 8];
                a_lo[ma][3] = *(const unsigned*)&As_lo[(r0 + g + 8) * ASTR + kc + 2 * q + 8];
            }
            #pragma unroll
            for (int na = 0; na < 4; na++) {
                int n0 = warp_n * 32 + na * 8;
                b_hi[na][0] = *(const unsigned*)&Bs_hi[(n0 + g) * ASTR + kc + 2 * q];
                b_hi[na][1] = *(const unsigned*)&Bs_hi[(n0 + g) * ASTR + kc + 2 * q + 8];
                b_lo[na][0] = *(const unsigned*)&Bs_lo[(n0 + g) * ASTR + kc + 2 * q];
                b_lo[na][1] = *(const unsigned*)&Bs_lo[(n0 + g) * ASTR + kc + 2 * q + 8];
            }
            #pragma unroll
            for (int ma = 0; ma < 2; ma++)
                #pragma unroll
                for (int na = 0; na < 4; na++) {
                    mma_bf16(acc[ma][na], a_hi[ma], b_hi[na]);
                    mma_bf16(acc[ma][na], a_hi[ma], b_lo[na]);
                    mma_bf16(acc[ma][na], a_lo[ma], b_hi[na]);
                }
        }
        __syncthreads();
    }

    // ---- epilogue: write h1 ----
    #pragma unroll
    for (int ma = 0; ma < 2; ma++) {
        int r0 = bm0 + warp_m * 32 + ma * 16 + g;
        #pragma unroll
        for (int na = 0; na < 4; na++) {
            int c = warp_n * 32 + na * 8 + 2 * q;
            if (r0 < NN)
                *(float2*)(g_h1 + (long)r0 * HC + c) = make_float2(acc[ma][na][0], acc[ma][na][1]);
            if (r0 + 8 < NN)
                *(float2*)(g_h1 + (long)(r0 + 8) * HC + c) = make_float2(acc[ma][na][2], acc[ma][na][3]);
        }
    }

    // ---- fused alpha1 ----
    float as_c0[4], as_c1[4], ad_c0[4], ad_c1[4];
    #pragma unroll
    for (int na = 0; na < 4; na++) {
        int hh = warp_n * 4 + na;
        as_c0[na] = a_s[hh * 8 + 2 * q];
        as_c1[na] = a_s[hh * 8 + 2 * q + 1];
        ad_c0[na] = a_d[hh * 8 + 2 * q];
        ad_c1[na] = a_d[hh * 8 + 2 * q + 1];
    }
    #pragma unroll
    for (int ma = 0; ma < 2; ma++)
        #pragma unroll
        for (int rh = 0; rh < 2; rh++) {
            float s[4], d[4];
            #pragma unroll
            for (int na = 0; na < 4; na++) {
                float h0 = acc[ma][na][rh * 2 + 0];
                float h1v = acc[ma][na][rh * 2 + 1];
                s[na] = h0 * as_c0[na] + h1v * as_c1[na];
                d[na] = h0 * ad_c0[na] + h1v * ad_c1[na];
            }
            #pragma unroll
            for (int na = 0; na < 4; na++) {
                s[na] += __shfl_xor_sync(0xffffffffu, s[na], 1);
                s[na] += __shfl_xor_sync(0xffffffffu, s[na], 2);
                d[na] += __shfl_xor_sync(0xffffffffu, d[na], 1);
                d[na] += __shfl_xor_sync(0xffffffffu, d[na], 2);
            }
            int row = bm0 + warp_m * 32 + ma * 16 + rh * 8 + g;
            if (q == 0 && row < NN) {
                *(float4*)(g_as1 + row * H1 + warp_n * 4) = make_float4(s[0], s[1], s[2], s[3]);
                *(float4*)(g_ad1 + row * H1 + warp_n * 4) = make_float4(d[0], d[1], d[2], d[3]);
            }
        }
}

// ---------------- layer-1 CSR aggregation: half-warp per edge, float4 gathers ----------------
__global__ void k_agg1(const float* __restrict__ b1) {
    int warp = (blockIdx.x * blockDim.x + threadIdx.x) >> 5;
    if (warp >= NN) return;
    int lane = threadIdx.x & 31;
    int half = lane >> 4;
    int l = lane & 15;
    int c = l * 4;
    int h = l >> 1;
    int n = warp;
    float adh = g_ad1[n * H1 + h];
    int beg = g_row[n], end = g_row[n + 1];
    float sum_p = 0.f, a0 = 0.f, a1 = 0.f, a2 = 0.f, a3 = 0.f;

    int j = beg + half;
    for (; j + 2 < end; j += 4) {
        int s0 = g_csr[j], s1 = g_csr[j + 2];
        float e0 = g_as1[s0 * H1 + h];
        float e1 = g_as1[s1 * H1 + h];
        float4 v0 = *(const float4*)(g_h1 + (long)s0 * HC + c);
        float4 v1 = *(const float4*)(g_h1 + (long)s1 * HC + c);
        float p0 = __expf(lrelu(e0 + adh));
        float p1 = __expf(lrelu(e1 + adh));
        sum_p += p0 + p1;
        a0 = fmaf(p0, v0.x, a0); a1 = fmaf(p0, v0.y, a1);
        a2 = fmaf(p0, v0.z, a2); a3 = fmaf(p0, v0.w, a3);
        a0 = fmaf(p1, v1.x, a0); a1 = fmaf(p1, v1.y, a1);
        a2 = fmaf(p1, v1.z, a2); a3 = fmaf(p1, v1.w, a3);
    }
    for (; j < end; j += 2) {
        int s0 = g_csr[j];
        float e0 = g_as1[s0 * H1 + h];
        float4 v0 = *(const float4*)(g_h1 + (long)s0 * HC + c);
        float p0 = __expf(lrelu(e0 + adh));
        sum_p += p0;
        a0 = fmaf(p0, v0.x, a0); a1 = fmaf(p0, v0.y, a1);
        a2 = fmaf(p0, v0.z, a2); a3 = fmaf(p0, v0.w, a3);
    }
    a0 += __shfl_xor_sync(0xffffffffu, a0, 16);
    a1 += __shfl_xor_sync(0xffffffffu, a1, 16);
    a2 += __shfl_xor_sync(0xffffffffu, a2, 16);
    a3 += __shfl_xor_sync(0xffffffffu, a3, 16);
    sum_p += __shfl_xor_sync(0xffffffffu, sum_p, 16);

    if (half == 0) {
        float inv = 1.0f / (sum_p + 1e-16f);
        float4 bb = *(const float4*)(b1 + c);
        float o0 = a0 * inv + bb.x;
        float o1 = a1 * inv + bb.y;
        float o2 = a2 * inv + bb.z;
        float o3 = a3 * inv + bb.w;
        o0 = o0 > 0.f ? o0 : (expf(o0) - 1.f);
        o1 = o1 > 0.f ? o1 : (expf(o1) - 1.f);
        o2 = o2 > 0.f ? o2 : (expf(o2) - 1.f);
        o3 = o3 > 0.f ? o3 : (expf(o3) - 1.f);
        *(float4*)(g_o1 + (long)n * HC + c) = make_float4(o0, o1, o2, o3);
    }
}

// ---------------- GEMM2 + fused alpha2 ----------------
__global__ void k_gemm2(const float* __restrict__ W2,
                        const float* __restrict__ a_s, const float* __restrict__ a_d) {
    __shared__ float Ws[HC * NC];
    __shared__ float rows[32 * HC];
    __shared__ float zsm[32 * 41];
    const int t = threadIdx.x;
    const int base = blockIdx.x * 32;
    for (int i = t; i < HC * NC; i += 256) Ws[i] = W2[i];
    for (int i = t; i < 32 * HC; i += 256) {
        int r = i / HC, k = i % HC;
        int gn = base + r;
        rows[i] = (gn < NN) ? g_o1[(long)gn * HC + k] : 0.0f;
    }
    __syncthreads();
    for (int o = t; o < 32 * NC; o += 256) {
        int r = o / NC, c = o % NC;
        int gn = base + r;
        float acc = 0.f;
        const float* rp = rows + r * HC;
        #pragma unroll
        for (int k = 0; k < HC; k++) acc = fmaf(rp[k], Ws[k * NC + c], acc);
        zsm[r * 41 + c] = acc;
        if (gn < NN) g_z[(long)gn * NC + c] = acc;
    }
    __syncthreads();
    if (t < 32) {
        int gn = base + t;
        if (gn < NN) {
            float s = 0.f, d = 0.f;
            #pragma unroll
            for (int c = 0; c < NC; c++) {
                float v = zsm[t * 41 + c];
                s = fmaf(v, a_s[c], s);
                d = fmaf(v, a_d[c], d);
            }
            g_as2[gn] = s;
            g_ad2[gn] = d;
        }
    }
}

// ---------------- layer-2 CSR aggregation + log_softmax ----------------
__global__ void k_agg2(float* __restrict__ out, const float* __restrict__ b2) {
    int warp = (blockIdx.x * blockDim.x + threadIdx.x) >> 5;
    if (warp >= NN) return;
    int lane = threadIdx.x & 31;
    int n = warp;
    float ad = g_ad2[n];
    int beg = g_row[n], end = g_row[n + 1];
    float sp = 0.f, acc_a = 0.f, acc_b = 0.f;
    int j = beg;
    for (; j + 4 <= end; j += 4) {
        int s0 = g_csr[j], s1 = g_csr[j + 1], s2 = g_csr[j + 2], s3 = g_csr[j + 3];
        float e0 = g_as2[s0], e1 = g_as2[s1], e2 = g_as2[s2], e3 = g_as2[s3];
        const float* z0 = g_z + (long)s0 * NC;
        const float* z1 = g_z + (long)s1 * NC;
        const float* z2 = g_z + (long)s2 * NC;
        const float* z3 = g_z + (long)s3 * NC;
        float w0 = z0[lane], w1 = z1[lane], w2 = z2[lane], w3 = z3[lane];
        float u0 = 0.f, u1 = 0.f, u2 = 0.f, u3 = 0.f;
        if (lane < 8) { u0 = z0[32 + lane]; u1 = z1[32 + lane]; u2 = z2[32 + lane]; u3 = z3[32 + lane]; }
        float p0 = __expf(lrelu(e0 + ad));
        float p1 = __expf(lrelu(e1 + ad));
        float p2 = __expf(lrelu(e2 + ad));
        float p3 = __expf(lrelu(e3 + ad));
        sp += (p0 + p1) + (p2 + p3);
        acc_a = fmaf(p0, w0, acc_a); acc_b = fmaf(p0, u0, acc_b);
        acc_a = fmaf(p1, w1, acc_a); acc_b = fmaf(p1, u1, acc_b);
        acc_a = fmaf(p2, w2, acc_a); acc_b = fmaf(p2, u2, acc_b);
        acc_a = fmaf(p3, w3, acc_a); acc_b = fmaf(p3, u3, acc_b);
    }
    for (; j < end; j++) {
        int src = g_csr[j];
        float p = __expf(lrelu(g_as2[src] + ad));
        sp += p;
        const float* zp = g_z + (long)src * NC;
        acc_a = fmaf(p, zp[lane], acc_a);
        if (lane < 8) acc_b = fmaf(p, zp[32 + lane], acc_b);
    }
    float inv = 1.0f / (sp + 1e-16f);
    float va = acc_a * inv + b2[lane];
    float vb = (lane < 8) ? acc_b * inv + b2[32 + lane] : -3.402823466e38f;
    float m = fmaxf(va, vb);
    #pragma unroll
    for (int off = 16; off > 0; off >>= 1)
        m = fmaxf(m, __shfl_xor_sync(0xffffffffu, m, off));
    float s = expf(va - m) + ((lane < 8) ? expf(vb - m) : 0.f);
    #pragma unroll
    for (int off = 16; off > 0; off >>= 1)
        s += __shfl_xor_sync(0xffffffffu, s, off);
    float lse = m + logf(s);
    float* op = out + (long)n * NC;
    op[lane] = va - lse;
    if (lane < 8) op[32 + lane] = vb - lse;
}

// ---------------- launch: fork-join two independent chains ----------------
// Chain A (origin stream): prepW -> gemm1        (tensor/DRAM bound, ~100us)
// Chain B (side stream):   init -> convert -> scan -> scatter  (L2/atomic bound, ~45us)
// join before agg1. Streams/events are host-side objects created on the first
// (uncaptured) call; the captured calls contain identical launch sequences.
extern "C" void kernel_launch(void* const* d_in, const int* in_sizes, int n_in,
                              void* d_out, int out_size) {
    const float* x    = (const float*)d_in[0];
    const void*  ei   = d_in[1];
    const float* W1   = (const float*)d_in[2];
    const float* as1  = (const float*)d_in[3];
    const float* ad1  = (const float*)d_in[4];
    const float* b1   = (const float*)d_in[5];
    const float* W2   = (const float*)d_in[6];
    const float* as2  = (const float*)d_in[7];
    const float* ad2  = (const float*)d_in[8];
    const float* b2   = (const float*)d_in[9];
    float*       out  = (float*)d_out;

    static cudaStream_t s2 = 0;
    static cudaEvent_t evFork = 0, evJoin = 0;
    if (s2 == 0) {
        cudaStreamCreateWithFlags(&s2, cudaStreamNonBlocking);
        cudaEventCreateWithFlags(&evFork, cudaEventDisableTiming);
        cudaEventCreateWithFlags(&evJoin, cudaEventDisableTiming);
    }

    const int TB = 256;

    // fork
    cudaEventRecord(evFork, 0);
    cudaStreamWaitEvent(s2, evFork, 0);

    // chain B (side stream): CSR build
    k_init   <<<(NN + TB - 1) / TB, TB, 0, s2>>>(ei);
    k_convert<<<(ETOT + TB - 1) / TB, TB, 0, s2>>>(ei);
    k_scan1  <<<NBLK, 1024, 0, s2>>>();
    k_scan2  <<<1, 32, 0, s2>>>();
    k_scan3  <<<(NN + TB - 1) / TB, TB, 0, s2>>>();
    k_scatter<<<(ETOT + TB - 1) / TB, TB, 0, s2>>>();
    cudaEventRecord(evJoin, s2);

    // chain A (origin stream): dense transform, concurrent with chain B
    k_prepW  <<<(FIN * HC + TB - 1) / TB, TB>>>(W1);
    k_gemm1  <<<(NN + 127) / 128, 256>>>(x, as1, ad1);

    // join
    cudaStreamWaitEvent(0, evJoin, 0);

    // serial tail
    k_agg1   <<<(NN * 32 + TB - 1) / TB, TB>>>(b1);
    k_gemm2  <<<(NN + 31) / 32, 256>>>(W2, as2, ad2);
    k_agg2   <<<(NN * 32 + TB - 1) / TB, TB>>>(out, b2);
}

// round 9
// speedup vs baseline: 1.1313x; 1.0053x over previous
#include <cuda_runtime.h>
#include <cuda_bf16.h>
#include <math.h>

#define NN 100000
#define EE 1600000
#define FIN 512
#define H1 8
#define C1 8
#define HC 64
#define NC 40
#define ETOT (EE + NN)
#define NEG_SLOPE 0.2f
#define NBLK 98   // ceil(NN/1024)

// ---------------- scratch ----------------
__device__ float g_h1[NN * HC];
__device__ float g_as1[NN * H1];
__device__ float g_ad1[NN * H1];
__device__ float g_o1[NN * HC];
__device__ float g_z[NN * NC];
__device__ float g_as2[NN];
__device__ float g_ad2[NN];
__device__ int   g_src[ETOT];
__device__ int   g_dst[ETOT];
__device__ int   g_deg[NN];
__device__ int   g_row[NN + 1];
__device__ int   g_cursor[NN];
__device__ int   g_bsum[NBLK];
__device__ int   g_csr[ETOT];
__device__ int   g_is64 = 1;   // monotone flag, converges identically every call
__device__ unsigned short g_W1T_hi[HC * FIN];
__device__ unsigned short g_W1T_lo[HC * FIN];

__device__ __forceinline__ float lrelu(float x) {
    return x > 0.0f ? x : NEG_SLOPE * x;
}

__device__ __forceinline__ void split_bf16(float v, unsigned short& hi, unsigned short& lo) {
    __nv_bfloat16 h = __float2bfloat16(v);
    float r = v - __bfloat162float(h);
    __nv_bfloat16 l = __float2bfloat16(r);
    hi = __bfloat16_as_ushort(h);
    lo = __bfloat16_as_ushort(l);
}

__device__ __forceinline__ void mma_bf16(float* c, const unsigned* a, const unsigned* b) {
    asm volatile(
        "mma.sync.aligned.m16n8k16.row.col.f32.bf16.bf16.f32 "
        "{%0,%1,%2,%3},{%4,%5,%6,%7},{%8,%9},{%0,%1,%2,%3};"
        : "+f"(c[0]), "+f"(c[1]), "+f"(c[2]), "+f"(c[3])
        : "r"(a[0]), "r"(a[1]), "r"(a[2]), "r"(a[3]), "r"(b[0]), "r"(b[1]));
}

// ---------------- init + dtype probe ----------------
__global__ void k_init(const void* __restrict__ ei) {
    int i = blockIdx.x * blockDim.x + threadIdx.x;
    if (i < NN) g_deg[i] = 0;
    if (i < 2048) {
        long long v = ((const long long*)ei)[i];
        if (v < 0 || v >= NN) atomicAnd(&g_is64, 0);
    }
}

// ---------------- edge conversion + degree count ----------------
__global__ void k_convert(const void* __restrict__ ei) {
    int idx = blockIdx.x * blockDim.x + threadIdx.x;
    if (idx >= ETOT) return;
    int s, d;
    if (idx < EE) {
        if (g_is64) {
            const long long* p = (const long long*)ei;
            s = (int)p[idx];
            d = (int)p[EE + idx];
        } else {
            const int* p = (const int*)ei;
            s = p[idx];
            d = p[EE + idx];
        }
    } else {
        s = d = idx - EE;
    }
    s = min(max(s, 0), NN - 1);
    d = min(max(d, 0), NN - 1);
    g_src[idx] = s;
    g_dst[idx] = d;
    atomicAdd(&g_deg[d], 1);
}

// ---------------- exclusive scan of degrees ----------------
__global__ void k_scan1() {
    __shared__ int sh[1024];
    int tid = threadIdx.x;
    int i = blockIdx.x * 1024 + tid;
    int v = (i < NN) ? g_deg[i] : 0;
    sh[tid] = v;
    __syncthreads();
    #pragma unroll
    for (int off = 1; off < 1024; off <<= 1) {
        int t = (tid >= off) ? sh[tid - off] : 0;
        __syncthreads();
        sh[tid] += t;
        __syncthreads();
    }
    if (i < NN) g_row[i] = sh[tid] - v;
    if (tid == 1023) g_bsum[blockIdx.x] = sh[1023];
}

__global__ void k_scan2() {
    if (threadIdx.x == 0) {
        int acc = 0;
        for (int b = 0; b < NBLK; b++) { int t = g_bsum[b]; g_bsum[b] = acc; acc += t; }
        g_row[NN] = acc;
    }
}

__global__ void k_scan3() {
    int i = blockIdx.x * blockDim.x + threadIdx.x;
    if (i < NN) {
        int r = g_row[i] + g_bsum[i >> 10];
        g_row[i] = r;
        g_cursor[i] = r;
    }
}

__global__ void k_scatter() {
    int idx = blockIdx.x * blockDim.x + threadIdx.x;
    if (idx >= ETOT) return;
    int d = g_dst[idx];
    int pos = atomicAdd(&g_cursor[d], 1);
    g_csr[pos] = g_src[idx];
}

// ---------------- W1 split/transpose ----------------
__global__ void k_prepW(const float* __restrict__ W1) {
    int i = blockIdx.x * blockDim.x + threadIdx.x;
    if (i >= FIN * HC) return;
    int k = i / HC, n = i % HC;
    unsigned short hi, lo;
    split_bf16(W1[i], hi, lo);
    g_W1T_hi[n * FIN + k] = hi;
    g_W1T_lo[n * FIN + k] = lo;
}

// ---------------- GEMM1 (bf16x3 tensor cores) + fused alpha1 epilogue ----------------
#define ASTR 40
__global__ __launch_bounds__(256) void k_gemm1(const float* __restrict__ x,
                                               const float* __restrict__ a_s,
                                               const float* __restrict__ a_d) {
    __shared__ unsigned short As_hi[128 * ASTR];
    __shared__ unsigned short As_lo[128 * ASTR];
    __shared__ unsigned short Bs_hi[64 * ASTR];
    __shared__ unsigned short Bs_lo[64 * ASTR];

    const int t = threadIdx.x;
    const int bm0 = blockIdx.x * 128;
    const int warp = t >> 5;
    const int lane = t & 31;
    const int g = lane >> 2;
    const int q = lane & 3;
    const int warp_m = warp >> 1;
    const int warp_n = warp & 1;

    float acc[2][4][4];
    #pragma unroll
    for (int i = 0; i < 2; i++)
        #pragma unroll
        for (int j = 0; j < 4; j++)
            #pragma unroll
            for (int r = 0; r < 4; r++) acc[i][j][r] = 0.f;

    for (int k0 = 0; k0 < FIN; k0 += 32) {
        #pragma unroll
        for (int i = 0; i < 4; i++) {
            int idx = i * 256 + t;
            int row = idx >> 3;
            int col = (idx & 7) * 4;
            float4 v = make_float4(0.f, 0.f, 0.f, 0.f);
            int gr = bm0 + row;
            if (gr < NN) v = *(const float4*)(x + (long)gr * FIN + k0 + col);
            unsigned short h0, l0, h1_, l1_, h2, l2, h3, l3;
            split_bf16(v.x, h0, l0);
            split_bf16(v.y, h1_, l1_);
            split_bf16(v.z, h2, l2);
            split_bf16(v.w, h3, l3);
            unsigned* ph = (unsigned*)&As_hi[row * ASTR + col];
            unsigned* pl = (unsigned*)&As_lo[row * ASTR + col];
            ph[0] = (unsigned)h0 | ((unsigned)h1_ << 16);
            ph[1] = (unsigned)h2 | ((unsigned)h3 << 16);
            pl[0] = (unsigned)l0 | ((unsigned)l1_ << 16);
            pl[1] = (unsigned)l2 | ((unsigned)l3 << 16);
        }
        {
            int row = t >> 2;
            int seg = t & 3;
            uint4 vh = *(const uint4*)&g_W1T_hi[row * FIN + k0 + seg * 8];
            uint4 vl = *(const uint4*)&g_W1T_lo[row * FIN + k0 + seg * 8];
            *(uint4*)&Bs_hi[row * ASTR + seg * 8] = vh;
            *(uint4*)&Bs_lo[row * ASTR + seg * 8] = vl;
        }
        __syncthreads();

        #pragma unroll
        for (int ka = 0; ka < 2; ka++) {
            const int kc = ka * 16;
            unsigned a_hi[2][4], a_lo[2][4], b_hi[4][2], b_lo[4][2];
            #pragma unroll
            for (int ma = 0; ma < 2; ma++) {
                int r0 = warp_m * 32 + ma * 16;
                a_hi[ma][0] = *(const unsigned*)&As_hi[(r0 + g) * ASTR + kc + 2 * q];
                a_hi[ma][1] = *(const unsigned*)&As_hi[(r0 + g + 8) * ASTR + kc + 2 * q];
                a_hi[ma][2] = *(const unsigned*)&As_hi[(r0 + g) * ASTR + kc + 2 * q + 8];
                a_hi[ma][3] = *(const unsigned*)&As_hi[(r0 + g + 8) * ASTR + kc + 2 * q + 8];
                a_lo[ma][0] = *(const unsigned*)&As_lo[(r0 + g) * ASTR + kc + 2 * q];
                a_lo[ma][1] = *(const unsigned*)&As_lo[(r0 + g + 8) * ASTR + kc + 2 * q];
                a_lo[ma][2] = *(const unsigned*)&As_lo[(r0 + g) * ASTR + kc + 2 * q + 8];
                a_lo[ma][3] = *(const unsigned*)&As_lo[(r0 + g + 8) * ASTR + kc + 2 * q + 8];
            }
            #pragma unroll
            for (int na = 0; na < 4; na++) {
                int n0 = warp_n * 32 + na * 8;
                b_hi[na][0] = *(const unsigned*)&Bs_hi[(n0 + g) * ASTR + kc + 2 * q];
                b_hi[na][1] = *(const unsigned*)&Bs_hi[(n0 + g) * ASTR + kc + 2 * q + 8];
                b_lo[na][0] = *(const unsigned*)&Bs_lo[(n0 + g) * ASTR + kc + 2 * q];
                b_lo[na][1] = *(const unsigned*)&Bs_lo[(n0 + g) * ASTR + kc + 2 * q + 8];
            }
            #pragma unroll
            for (int ma = 0; ma < 2; ma++)
                #pragma unroll
                for (int na = 0; na < 4; na++) {
                    mma_bf16(acc[ma][na], a_hi[ma], b_hi[na]);
                    mma_bf16(acc[ma][na], a_hi[ma], b_lo[na]);
                    mma_bf16(acc[ma][na], a_lo[ma], b_hi[na]);
                }
        }
        __syncthreads();
    }

    // ---- epilogue: write h1 ----
    #pragma unroll
    for (int ma = 0; ma < 2; ma++) {
        int r0 = bm0 + warp_m * 32 + ma * 16 + g;
        #pragma unroll
        for (int na = 0; na < 4; na++) {
            int c = warp_n * 32 + na * 8 + 2 * q;
            if (r0 < NN)
                *(float2*)(g_h1 + (long)r0 * HC + c) = make_float2(acc[ma][na][0], acc[ma][na][1]);
            if (r0 + 8 < NN)
                *(float2*)(g_h1 + (long)(r0 + 8) * HC + c) = make_float2(acc[ma][na][2], acc[ma][na][3]);
        }
    }

    // ---- fused alpha1 ----
    float as_c0[4], as_c1[4], ad_c0[4], ad_c1[4];
    #pragma unroll
    for (int na = 0; na < 4; na++) {
        int hh = warp_n * 4 + na;
        as_c0[na] = a_s[hh * 8 + 2 * q];
        as_c1[na] = a_s[hh * 8 + 2 * q + 1];
        ad_c0[na] = a_d[hh * 8 + 2 * q];
        ad_c1[na] = a_d[hh * 8 + 2 * q + 1];
    }
    #pragma unroll
    for (int ma = 0; ma < 2; ma++)
        #pragma unroll
        for (int rh = 0; rh < 2; rh++) {
            float s[4], d[4];
            #pragma unroll
            for (int na = 0; na < 4; na++) {
                float h0 = acc[ma][na][rh * 2 + 0];
                float h1v = acc[ma][na][rh * 2 + 1];
                s[na] = h0 * as_c0[na] + h1v * as_c1[na];
                d[na] = h0 * ad_c0[na] + h1v * ad_c1[na];
            }
            #pragma unroll
            for (int na = 0; na < 4; na++) {
                s[na] += __shfl_xor_sync(0xffffffffu, s[na], 1);
                s[na] += __shfl_xor_sync(0xffffffffu, s[na], 2);
                d[na] += __shfl_xor_sync(0xffffffffu, d[na], 1);
                d[na] += __shfl_xor_sync(0xffffffffu, d[na], 2);
            }
            int row = bm0 + warp_m * 32 + ma * 16 + rh * 8 + g;
            if (q == 0 && row < NN) {
                *(float4*)(g_as1 + row * H1 + warp_n * 4) = make_float4(s[0], s[1], s[2], s[3]);
                *(float4*)(g_ad1 + row * H1 + warp_n * 4) = make_float4(d[0], d[1], d[2], d[3]);
            }
        }
}

// ---------------- layer-1 CSR aggregation: quarter-warp per edge ----------------
// lane = qt*8 + l; lane owns head l (channels 8l..8l+7); 4 edges in flight, unroll x2.
__global__ void k_agg1(const float* __restrict__ b1) {
    int warp = (blockIdx.x * blockDim.x + threadIdx.x) >> 5;
    if (warp >= NN) return;
    int lane = threadIdx.x & 31;
    int qt = lane >> 3;            // quarter: which edge of the group of 4
    int l = lane & 7;              // head index == channel block
    int n = warp;
    float adh = g_ad1[n * H1 + l];
    int beg = g_row[n], end = g_row[n + 1];
    float sp = 0.f;
    float A[8] = {0.f, 0.f, 0.f, 0.f, 0.f, 0.f, 0.f, 0.f};

    int j = beg + qt;
    for (; j + 4 < end; j += 8) {  // edges j and j+4 for this quarter
        int s0 = g_csr[j], s1 = g_csr[j + 4];
        float e0 = g_as1[s0 * H1 + l];
        float e1 = g_as1[s1 * H1 + l];
        const float4* r0 = (const float4*)(g_h1 + (long)s0 * HC + l * 8);
        const float4* r1 = (const float4*)(g_h1 + (long)s1 * HC + l * 8);
        float4 v00 = r0[0], v01 = r0[1];
        float4 v10 = r1[0], v11 = r1[1];
        float p0 = __expf(lrelu(e0 + adh));
        float p1 = __expf(lrelu(e1 + adh));
        sp += p0 + p1;
        A[0] = fmaf(p0, v00.x, A[0]); A[1] = fmaf(p0, v00.y, A[1]);
        A[2] = fmaf(p0, v00.z, A[2]); A[3] = fmaf(p0, v00.w, A[3]);
        A[4] = fmaf(p0, v01.x, A[4]); A[5] = fmaf(p0, v01.y, A[5]);
        A[6] = fmaf(p0, v01.z, A[6]); A[7] = fmaf(p0, v01.w, A[7]);
        A[0] = fmaf(p1, v10.x, A[0]); A[1] = fmaf(p1, v10.y, A[1]);
        A[2] = fmaf(p1, v10.z, A[2]); A[3] = fmaf(p1, v10.w, A[3]);
        A[4] = fmaf(p1, v11.x, A[4]); A[5] = fmaf(p1, v11.y, A[5]);
        A[6] = fmaf(p1, v11.z, A[6]); A[7] = fmaf(p1, v11.w, A[7]);
    }
    for (; j < end; j += 4) {
        int s0 = g_csr[j];
        float e0 = g_as1[s0 * H1 + l];
        const float4* r0 = (const float4*)(g_h1 + (long)s0 * HC + l * 8);
        float4 v00 = r0[0], v01 = r0[1];
        float p0 = __expf(lrelu(e0 + adh));
        sp += p0;
        A[0] = fmaf(p0, v00.x, A[0]); A[1] = fmaf(p0, v00.y, A[1]);
        A[2] = fmaf(p0, v00.z, A[2]); A[3] = fmaf(p0, v00.w, A[3]);
        A[4] = fmaf(p0, v01.x, A[4]); A[5] = fmaf(p0, v01.y, A[5]);
        A[6] = fmaf(p0, v01.z, A[6]); A[7] = fmaf(p0, v01.w, A[7]);
    }
    // combine the four quarters (same head l lives at lane distance 8,16,24)
    #pragma unroll
    for (int i = 0; i < 8; i++) {
        A[i] += __shfl_xor_sync(0xffffffffu, A[i], 8);
        A[i] += __shfl_xor_sync(0xffffffffu, A[i], 16);
    }
    sp += __shfl_xor_sync(0xffffffffu, sp, 8);
    sp += __shfl_xor_sync(0xffffffffu, sp, 16);

    if (qt == 0) {
        float inv = 1.0f / (sp + 1e-16f);
        float4 b0 = *(const float4*)(b1 + l * 8);
        float4 b1v = *(const float4*)(b1 + l * 8 + 4);
        float o[8];
        o[0] = A[0] * inv + b0.x; o[1] = A[1] * inv + b0.y;
        o[2] = A[2] * inv + b0.z; o[3] = A[3] * inv + b0.w;
        o[4] = A[4] * inv + b1v.x; o[5] = A[5] * inv + b1v.y;
        o[6] = A[6] * inv + b1v.z; o[7] = A[7] * inv + b1v.w;
        #pragma unroll
        for (int i = 0; i < 8; i++) o[i] = o[i] > 0.f ? o[i] : (expf(o[i]) - 1.f);
        float* op = g_o1 + (long)n * HC + l * 8;
        *(float4*)(op + 0) = make_float4(o[0], o[1], o[2], o[3]);
        *(float4*)(op + 4) = make_float4(o[4], o[5], o[6], o[7]);
    }
}

// ---------------- GEMM2 + fused alpha2 ----------------
__global__ void k_gemm2(const float* __restrict__ W2,
                        const float* __restrict__ a_s, const float* __restrict__ a_d) {
    __shared__ float Ws[HC * NC];
    __shared__ float rows[32 * HC];
    __shared__ float zsm[32 * 41];
    const int t = threadIdx.x;
    const int base = blockIdx.x * 32;
    for (int i = t; i < HC * NC; i += 256) Ws[i] = W2[i];
    for (int i = t; i < 32 * HC; i += 256) {
        int r = i / HC, k = i % HC;
        int gn = base + r;
        rows[i] = (gn < NN) ? g_o1[(long)gn * HC + k] : 0.0f;
    }
    __syncthreads();
    for (int o = t; o < 32 * NC; o += 256) {
        int r = o / NC, c = o % NC;
        int gn = base + r;
        float acc = 0.f;
        const float* rp = rows + r * HC;
        #pragma unroll
        for (int k = 0; k < HC; k++) acc = fmaf(rp[k], Ws[k * NC + c], acc);
        zsm[r * 41 + c] = acc;
        if (gn < NN) g_z[(long)gn * NC + c] = acc;
    }
    __syncthreads();
    if (t < 32) {
        int gn = base + t;
        if (gn < NN) {
            float s = 0.f, d = 0.f;
            #pragma unroll
            for (int c = 0; c < NC; c++) {
                float v = zsm[t * 41 + c];
                s = fmaf(v, a_s[c], s);
                d = fmaf(v, a_d[c], d);
            }
            g_as2[gn] = s;
            g_ad2[gn] = d;
        }
    }
}

// ---------------- layer-2 CSR aggregation + log_softmax: half-warp per edge ----------------
// lane = half*16 + l; lanes l<10 own channels 4l..4l+3 (float4); 2 edges in flight, unroll x2.
__global__ void k_agg2(float* __restrict__ out, const float* __restrict__ b2) {
    int warp = (blockIdx.x * blockDim.x + threadIdx.x) >> 5;
    if (warp >= NN) return;
    int lane = threadIdx.x & 31;
    int half = lane >> 4;
    int l = lane & 15;
    int n = warp;
    float ad = g_ad2[n];
    int beg = g_row[n], end = g_row[n + 1];
    bool ldz = (l < 10);
    float sp = 0.f;
    float A[4] = {0.f, 0.f, 0.f, 0.f};

    int j = beg + half;
    for (; j + 2 < end; j += 4) {   // edges j and j+2 for this half
        int s0 = g_csr[j], s1 = g_csr[j + 2];
        float e0 = g_as2[s0], e1 = g_as2[s1];
        float4 v0 = make_float4(0.f, 0.f, 0.f, 0.f), v1 = v0;
        if (ldz) {
            v0 = *(const float4*)(g_z + (long)s0 * NC + l * 4);
            v1 = *(const float4*)(g_z + (long)s1 * NC + l * 4);
        }
        float p0 = __expf(lrelu(e0 + ad));
        float p1 = __expf(lrelu(e1 + ad));
        sp += p0 + p1;
        A[0] = fmaf(p0, v0.x, A[0]); A[1] = fmaf(p0, v0.y, A[1]);
        A[2] = fmaf(p0, v0.z, A[2]); A[3] = fmaf(p0, v0.w, A[3]);
        A[0] = fmaf(p1, v1.x, A[0]); A[1] = fmaf(p1, v1.y, A[1]);
        A[2] = fmaf(p1, v1.z, A[2]); A[3] = fmaf(p1, v1.w, A[3]);
    }
    for (; j < end; j += 2) {
        int s0 = g_csr[j];
        float e0 = g_as2[s0];
        float4 v0 = make_float4(0.f, 0.f, 0.f, 0.f);
        if (ldz) v0 = *(const float4*)(g_z + (long)s0 * NC + l * 4);
        float p0 = __expf(lrelu(e0 + ad));
        sp += p0;
        A[0] = fmaf(p0, v0.x, A[0]); A[1] = fmaf(p0, v0.y, A[1]);
        A[2] = fmaf(p0, v0.z, A[2]); A[3] = fmaf(p0, v0.w, A[3]);
    }
    // combine halves
    #pragma unroll
    for (int i = 0; i < 4; i++) A[i] += __shfl_xor_sync(0xffffffffu, A[i], 16);
    sp += __shfl_xor_sync(0xffffffffu, sp, 16);

    bool act = (half == 0) && ldz;
    float inv = 1.0f / (sp + 1e-16f);
    float v[4];
    float mloc = -3.402823466e38f;
    if (act) {
        float4 bb = *(const float4*)(b2 + l * 4);
        v[0] = A[0] * inv + bb.x; v[1] = A[1] * inv + bb.y;
        v[2] = A[2] * inv + bb.z; v[3] = A[3] * inv + bb.w;
        mloc = fmaxf(fmaxf(v[0], v[1]), fmaxf(v[2], v[3]));
    }
    // warp-wide max and sum (inactive lanes contribute neutral values)
    float m = mloc;
    #pragma unroll
    for (int off = 16; off > 0; off >>= 1)
        m = fmaxf(m, __shfl_xor_sync(0xffffffffu, m, off));
    float sloc = 0.f;
    if (act)
        sloc = expf(v[0] - m) + expf(v[1] - m) + expf(v[2] - m) + expf(v[3] - m);
    float s = sloc;
    #pragma unroll
    for (int off = 16; off > 0; off >>= 1)
        s += __shfl_xor_sync(0xffffffffu, s, off);
    float lse = m + logf(s);
    if (act) {
        float* op = out + (long)n * NC + l * 4;
        *(float4*)op = make_float4(v[0] - lse, v[1] - lse, v[2] - lse, v[3] - lse);
    }
}

// ---------------- launch: fork-join two independent chains ----------------
extern "C" void kernel_launch(void* const* d_in, const int* in_sizes, int n_in,
                              void* d_out, int out_size) {
    const float* x    = (const float*)d_in[0];
    const void*  ei   = d_in[1];
    const float* W1   = (const float*)d_in[2];
    const float* as1  = (const float*)d_in[3];
    const float* ad1  = (const float*)d_in[4];
    const float* b1   = (const float*)d_in[5];
    const float* W2   = (const float*)d_in[6];
    const float* as2  = (const float*)d_in[7];
    const float* ad2  = (const float*)d_in[8];
    const float* b2   = (const float*)d_in[9];
    float*       out  = (float*)d_out;

    static cudaStream_t s2 = 0;
    static cudaEvent_t evFork = 0, evJoin = 0;
    if (s2 == 0) {
        cudaStreamCreateWithFlags(&s2, cudaStreamNonBlocking);
        cudaEventCreateWithFlags(&evFork, cudaEventDisableTiming);
        cudaEventCreateWithFlags(&evJoin, cudaEventDisableTiming);
    }

    const int TB = 256;

    // fork
    cudaEventRecord(evFork, 0);
    cudaStreamWaitEvent(s2, evFork, 0);

    // chain B (side stream): CSR build
    k_init   <<<(NN + TB - 1) / TB, TB, 0, s2>>>(ei);
    k_convert<<<(ETOT + TB - 1) / TB, TB, 0, s2>>>(ei);
    k_scan1  <<<NBLK, 1024, 0, s2>>>();
    k_scan2  <<<1, 32, 0, s2>>>();
    k_scan3  <<<(NN + TB - 1) / TB, TB, 0, s2>>>();
    k_scatter<<<(ETOT + TB - 1) / TB, TB, 0, s2>>>();
    cudaEventRecord(evJoin, s2);

    // chain A (origin stream): dense transform, concurrent with chain B
    k_prepW  <<<(FIN * HC + TB - 1) / TB, TB>>>(W1);
    k_gemm1  <<<(NN + 127) / 128, 256>>>(x, as1, ad1);

    // join
    cudaStreamWaitEvent(0, evJoin, 0);

    // serial tail
    k_agg1   <<<(NN * 32 + TB - 1) / TB, TB>>>(b1);
    k_gemm2  <<<(NN + 31) / 32, 256>>>(W2, as2, ad2);
    k_agg2   <<<(NN * 32 + TB - 1) / TB, TB>>>(out, b2);
}

// round 11
// speedup vs baseline: 1.1451x; 1.0122x over previous
#include <cuda_runtime.h>
#include <cuda_bf16.h>
#include <math.h>

#define NN 100000
#define EE 1600000
#define FIN 512
#define H1 8
#define C1 8
#define HC 64
#define NC 40
#define ETOT (EE + NN)
#define NEG_SLOPE 0.2f
#define NBLK 98   // ceil(NN/1024)

// ---------------- scratch ----------------
__device__ float g_h1[NN * HC];
__device__ float g_as1[NN * H1];
__device__ float g_ad1[NN * H1];
__device__ float g_o1[NN * HC];
__device__ float g_z[NN * NC];
__device__ float g_as2[NN];
__device__ float g_ad2[NN];
__device__ int   g_src[ETOT];
__device__ int   g_dst[ETOT];
__device__ int   g_deg[NN];
__device__ int   g_row[NN + 1];
__device__ int   g_cursor[NN];
__device__ int   g_bsum[NBLK];
__device__ int   g_csr[ETOT];
__device__ int   g_is64 = 1;   // monotone flag, converges identically every call
__device__ unsigned short g_W1T_hi[HC * FIN];
__device__ unsigned short g_W1T_lo[HC * FIN];

__device__ __forceinline__ float lrelu(float x) {
    return x > 0.0f ? x : NEG_SLOPE * x;
}

__device__ __forceinline__ void split_bf16(float v, unsigned short& hi, unsigned short& lo) {
    __nv_bfloat16 h = __float2bfloat16(v);
    float r = v - __bfloat162float(h);
    __nv_bfloat16 l = __float2bfloat16(r);
    hi = __bfloat16_as_ushort(h);
    lo = __bfloat16_as_ushort(l);
}

__device__ __forceinline__ void mma_bf16(float* c, const unsigned* a, const unsigned* b) {
    asm volatile(
        "mma.sync.aligned.m16n8k16.row.col.f32.bf16.bf16.f32 "
        "{%0,%1,%2,%3},{%4,%5,%6,%7},{%8,%9},{%0,%1,%2,%3};"
        : "+f"(c[0]), "+f"(c[1]), "+f"(c[2]), "+f"(c[3])
        : "r"(a[0]), "r"(a[1]), "r"(a[2]), "r"(a[3]), "r"(b[0]), "r"(b[1]));
}

__device__ __forceinline__ void ldsm4(unsigned* r, unsigned addr) {
    asm volatile("ldmatrix.sync.aligned.m8n8.x4.shared.b16 {%0,%1,%2,%3}, [%4];"
                 : "=r"(r[0]), "=r"(r[1]), "=r"(r[2]), "=r"(r[3]) : "r"(addr));
}

// ---------------- init + dtype probe ----------------
__global__ void k_init(const void* __restrict__ ei) {
    int i = blockIdx.x * blockDim.x + threadIdx.x;
    if (i < NN) g_deg[i] = 0;
    if (i < 2048) {
        long long v = ((const long long*)ei)[i];
        if (v < 0 || v >= NN) atomicAnd(&g_is64, 0);
    }
}

// ---------------- edge conversion + degree count ----------------
__global__ void k_convert(const void* __restrict__ ei) {
    int idx = blockIdx.x * blockDim.x + threadIdx.x;
    if (idx >= ETOT) return;
    int s, d;
    if (idx < EE) {
        if (g_is64) {
            const long long* p = (const long long*)ei;
            s = (int)p[idx];
            d = (int)p[EE + idx];
        } else {
            const int* p = (const int*)ei;
            s = p[idx];
            d = p[EE + idx];
        }
    } else {
        s = d = idx - EE;
    }
    s = min(max(s, 0), NN - 1);
    d = min(max(d, 0), NN - 1);
    g_src[idx] = s;
    g_dst[idx] = d;
    atomicAdd(&g_deg[d], 1);
}

// ---------------- exclusive scan of degrees ----------------
__global__ void k_scan1() {
    __shared__ int sh[1024];
    int tid = threadIdx.x;
    int i = blockIdx.x * 1024 + tid;
    int v = (i < NN) ? g_deg[i] : 0;
    sh[tid] = v;
    __syncthreads();
    #pragma unroll
    for (int off = 1; off < 1024; off <<= 1) {
        int t = (tid >= off) ? sh[tid - off] : 0;
        __syncthreads();
        sh[tid] += t;
        __syncthreads();
    }
    if (i < NN) g_row[i] = sh[tid] - v;
    if (tid == 1023) g_bsum[blockIdx.x] = sh[1023];
}

__global__ void k_scan2() {
    if (threadIdx.x == 0) {
        int acc = 0;
        for (int b = 0; b < NBLK; b++) { int t = g_bsum[b]; g_bsum[b] = acc; acc += t; }
        g_row[NN] = acc;
    }
}

__global__ void k_scan3() {
    int i = blockIdx.x * blockDim.x + threadIdx.x;
    if (i < NN) {
        int r = g_row[i] + g_bsum[i >> 10];
        g_row[i] = r;
        g_cursor[i] = r;
    }
}

__global__ void k_scatter() {
    int idx = blockIdx.x * blockDim.x + threadIdx.x;
    if (idx >= ETOT) return;
    int d = g_dst[idx];
    int pos = atomicAdd(&g_cursor[d], 1);
    g_csr[pos] = g_src[idx];
}

// ---------------- W1 split/transpose ----------------
__global__ void k_prepW(const float* __restrict__ W1) {
    int i = blockIdx.x * blockDim.x + threadIdx.x;
    if (i >= FIN * HC) return;
    int k = i / HC, n = i % HC;
    unsigned short hi, lo;
    split_bf16(W1[i], hi, lo);
    g_W1T_hi[n * FIN + k] = hi;
    g_W1T_lo[n * FIN + k] = lo;
}

// ---------------- GEMM1 (bf16x3 tensor cores, ldmatrix fragments) + fused alpha1 ----------------
#define ASTR 40
__global__ __launch_bounds__(256) void k_gemm1(const float* __restrict__ x,
                                               const float* __restrict__ a_s,
                                               const float* __restrict__ a_d) {
    __shared__ __align__(16) unsigned short As_hi[128 * ASTR];
    __shared__ __align__(16) unsigned short As_lo[128 * ASTR];
    __shared__ __align__(16) unsigned short Bs_hi[64 * ASTR];
    __shared__ __align__(16) unsigned short Bs_lo[64 * ASTR];

    const int t = threadIdx.x;
    const int bm0 = blockIdx.x * 128;
    const int warp = t >> 5;
    const int lane = t & 31;
    const int g = lane >> 2;
    const int q = lane & 3;
    const int warp_m = warp >> 1;
    const int warp_n = warp & 1;

    // ldmatrix lane offset: matrix id = lane/8, row-in-matrix = lane%8
    // matrices: 0 = rows 0-7/k 0-7, 1 = rows 8-15/k 0-7, 2 = rows 0-7/k 8-15, 3 = rows 8-15/k 8-15
    const int mat = lane >> 3;
    const int rowin = lane & 7;
    const int lm_off = ((mat & 1) * 8 + rowin) * ASTR + (mat >> 1) * 8;  // elements

    const unsigned ash = (unsigned)__cvta_generic_to_shared(As_hi);
    const unsigned asl = (unsigned)__cvta_generic_to_shared(As_lo);
    const unsigned bsh = (unsigned)__cvta_generic_to_shared(Bs_hi);
    const unsigned bsl = (unsigned)__cvta_generic_to_shared(Bs_lo);

    float acc[2][4][4];
    #pragma unroll
    for (int i = 0; i < 2; i++)
        #pragma unroll
        for (int j = 0; j < 4; j++)
            #pragma unroll
            for (int r = 0; r < 4; r++) acc[i][j][r] = 0.f;

    for (int k0 = 0; k0 < FIN; k0 += 32) {
        #pragma unroll
        for (int i = 0; i < 4; i++) {
            int idx = i * 256 + t;
            int row = idx >> 3;
            int col = (idx & 7) * 4;
            float4 v = make_float4(0.f, 0.f, 0.f, 0.f);
            int gr = bm0 + row;
            if (gr < NN) v = *(const float4*)(x + (long)gr * FIN + k0 + col);
            unsigned short h0, l0, h1_, l1_, h2, l2, h3, l3;
            split_bf16(v.x, h0, l0);
            split_bf16(v.y, h1_, l1_);
            split_bf16(v.z, h2, l2);
            split_bf16(v.w, h3, l3);
            unsigned* ph = (unsigned*)&As_hi[row * ASTR + col];
            unsigned* pl = (unsigned*)&As_lo[row * ASTR + col];
            ph[0] = (unsigned)h0 | ((unsigned)h1_ << 16);
            ph[1] = (unsigned)h2 | ((unsigned)h3 << 16);
            pl[0] = (unsigned)l0 | ((unsigned)l1_ << 16);
            pl[1] = (unsigned)l2 | ((unsigned)l3 << 16);
        }
        {
            int row = t >> 2;
            int seg = t & 3;
            uint4 vh = *(const uint4*)&g_W1T_hi[row * FIN + k0 + seg * 8];
            uint4 vl = *(const uint4*)&g_W1T_lo[row * FIN + k0 + seg * 8];
            *(uint4*)&Bs_hi[row * ASTR + seg * 8] = vh;
            *(uint4*)&Bs_lo[row * ASTR + seg * 8] = vl;
        }
        __syncthreads();

        #pragma unroll
        for (int ka = 0; ka < 2; ka++) {
            const int kc = ka * 16;
            unsigned a_hi[2][4], a_lo[2][4], b_hi[4][2], b_lo[4][2];
            // A fragments: one ldmatrix.x4 per (ma, hi/lo); reg order matches a0..a3
            #pragma unroll
            for (int ma = 0; ma < 2; ma++) {
                int r0 = warp_m * 32 + ma * 16;
                unsigned eoff = (unsigned)((r0 * ASTR + kc + lm_off) * 2);
                ldsm4(a_hi[ma], ash + eoff);
                ldsm4(a_lo[ma], asl + eoff);
            }
            // B fragments: one ldmatrix.x4 covers two na blocks.
            // reg r[0] = n 0-7 / k 0-7, r[1] = n 8-15 / k 0-7,
            //     r[2] = n 0-7 / k 8-15, r[3] = n 8-15 / k 8-15.
            // Per na we need {k0-7, k8-15} -> b[2p]={r0,r2}, b[2p+1]={r1,r3}.
            #pragma unroll
            for (int p = 0; p < 2; p++) {
                int n0 = warp_n * 32 + p * 16;
                unsigned eoff = (unsigned)((n0 * ASTR + kc + lm_off) * 2);
                unsigned rh[4], rl[4];
                ldsm4(rh, bsh + eoff);
                ldsm4(rl, bsl + eoff);
                b_hi[2 * p][0] = rh[0]; b_hi[2 * p][1] = rh[2];
                b_hi[2 * p + 1][0] = rh[1]; b_hi[2 * p + 1][1] = rh[3];
                b_lo[2 * p][0] = rl[0]; b_lo[2 * p][1] = rl[2];
                b_lo[2 * p + 1][0] = rl[1]; b_lo[2 * p + 1][1] = rl[3];
            }
            #pragma unroll
            for (int ma = 0; ma < 2; ma++)
                #pragma unroll
                for (int na = 0; na < 4; na++) {
                    mma_bf16(acc[ma][na], a_hi[ma], b_hi[na]);
                    mma_bf16(acc[ma][na], a_hi[ma], b_lo[na]);
                    mma_bf16(acc[ma][na], a_lo[ma], b_hi[na]);
                }
        }
        __syncthreads();
    }

    // ---- epilogue: write h1 ----
    #pragma unroll
    for (int ma = 0; ma < 2; ma++) {
        int r0 = bm0 + warp_m * 32 + ma * 16 + g;
        #pragma unroll
        for (int na = 0; na < 4; na++) {
            int c = warp_n * 32 + na * 8 + 2 * q;
            if (r0 < NN)
                *(float2*)(g_h1 + (long)r0 * HC + c) = make_float2(acc[ma][na][0], acc[ma][na][1]);
            if (r0 + 8 < NN)
                *(float2*)(g_h1 + (long)(r0 + 8) * HC + c) = make_float2(acc[ma][na][2], acc[ma][na][3]);
        }
    }

    // ---- fused alpha1 ----
    float as_c0[4], as_c1[4], ad_c0[4], ad_c1[4];
    #pragma unroll
    for (int na = 0; na < 4; na++) {
        int hh = warp_n * 4 + na;
        as_c0[na] = a_s[hh * 8 + 2 * q];
        as_c1[na] = a_s[hh * 8 + 2 * q + 1];
        ad_c0[na] = a_d[hh * 8 + 2 * q];
        ad_c1[na] = a_d[hh * 8 + 2 * q + 1];
    }
    #pragma unroll
    for (int ma = 0; ma < 2; ma++)
        #pragma unroll
        for (int rh = 0; rh < 2; rh++) {
            float s[4], d[4];
            #pragma unroll
            for (int na = 0; na < 4; na++) {
                float h0 = acc[ma][na][rh * 2 + 0];
                float h1v = acc[ma][na][rh * 2 + 1];
                s[na] = h0 * as_c0[na] + h1v * as_c1[na];
                d[na] = h0 * ad_c0[na] + h1v * ad_c1[na];
            }
            #pragma unroll
            for (int na = 0; na < 4; na++) {
                s[na] += __shfl_xor_sync(0xffffffffu, s[na], 1);
                s[na] += __shfl_xor_sync(0xffffffffu, s[na], 2);
                d[na] += __shfl_xor_sync(0xffffffffu, d[na], 1);
                d[na] += __shfl_xor_sync(0xffffffffu, d[na], 2);
            }
            int row = bm0 + warp_m * 32 + ma * 16 + rh * 8 + g;
            if (q == 0 && row < NN) {
                *(float4*)(g_as1 + row * H1 + warp_n * 4) = make_float4(s[0], s[1], s[2], s[3]);
                *(float4*)(g_ad1 + row * H1 + warp_n * 4) = make_float4(d[0], d[1], d[2], d[3]);
            }
        }
}

// ---------------- layer-1 CSR aggregation: quarter-warp per edge ----------------
__global__ void k_agg1(const float* __restrict__ b1) {
    int warp = (blockIdx.x * blockDim.x + threadIdx.x) >> 5;
    if (warp >= NN) return;
    int lane = threadIdx.x & 31;
    int qt = lane >> 3;
    int l = lane & 7;
    int n = warp;
    float adh = g_ad1[n * H1 + l];
    int beg = g_row[n], end = g_row[n + 1];
    float sp = 0.f;
    float A[8] = {0.f, 0.f, 0.f, 0.f, 0.f, 0.f, 0.f, 0.f};

    int j = beg + qt;
    for (; j + 4 < end; j += 8) {
        int s0 = g_csr[j], s1 = g_csr[j + 4];
        float e0 = g_as1[s0 * H1 + l];
        float e1 = g_as1[s1 * H1 + l];
        const float4* r0 = (const float4*)(g_h1 + (long)s0 * HC + l * 8);
        const float4* r1 = (const float4*)(g_h1 + (long)s1 * HC + l * 8);
        float4 v00 = r0[0], v01 = r0[1];
        float4 v10 = r1[0], v11 = r1[1];
        float p0 = __expf(lrelu(e0 + adh));
        float p1 = __expf(lrelu(e1 + adh));
        sp += p0 + p1;
        A[0] = fmaf(p0, v00.x, A[0]); A[1] = fmaf(p0, v00.y, A[1]);
        A[2] = fmaf(p0, v00.z, A[2]); A[3] = fmaf(p0, v00.w, A[3]);
        A[4] = fmaf(p0, v01.x, A[4]); A[5] = fmaf(p0, v01.y, A[5]);
        A[6] = fmaf(p0, v01.z, A[6]); A[7] = fmaf(p0, v01.w, A[7]);
        A[0] = fmaf(p1, v10.x, A[0]); A[1] = fmaf(p1, v10.y, A[1]);
        A[2] = fmaf(p1, v10.z, A[2]); A[3] = fmaf(p1, v10.w, A[3]);
        A[4] = fmaf(p1, v11.x, A[4]); A[5] = fmaf(p1, v11.y, A[5]);
        A[6] = fmaf(p1, v11.z, A[6]); A[7] = fmaf(p1, v11.w, A[7]);
    }
    for (; j < end; j += 4) {
        int s0 = g_csr[j];
        float e0 = g_as1[s0 * H1 + l];
        const float4* r0 = (const float4*)(g_h1 + (long)s0 * HC + l * 8);
        float4 v00 = r0[0], v01 = r0[1];
        float p0 = __expf(lrelu(e0 + adh));
        sp += p0;
        A[0] = fmaf(p0, v00.x, A[0]); A[1] = fmaf(p0, v00.y, A[1]);
        A[2] = fmaf(p0, v00.z, A[2]); A[3] = fmaf(p0, v00.w, A[3]);
        A[4] = fmaf(p0, v01.x, A[4]); A[5] = fmaf(p0, v01.y, A[5]);
        A[6] = fmaf(p0, v01.z, A[6]); A[7] = fmaf(p0, v01.w, A[7]);
    }
    #pragma unroll
    for (int i = 0; i < 8; i++) {
        A[i] += __shfl_xor_sync(0xffffffffu, A[i], 8);
        A[i] += __shfl_xor_sync(0xffffffffu, A[i], 16);
    }
    sp += __shfl_xor_sync(0xffffffffu, sp, 8);
    sp += __shfl_xor_sync(0xffffffffu, sp, 16);

    if (qt == 0) {
        float inv = 1.0f / (sp + 1e-16f);
        float4 b0 = *(const float4*)(b1 + l * 8);
        float4 b1v = *(const float4*)(b1 + l * 8 + 4);
        float o[8];
        o[0] = A[0] * inv + b0.x; o[1] = A[1] * inv + b0.y;
        o[2] = A[2] * inv + b0.z; o[3] = A[3] * inv + b0.w;
        o[4] = A[4] * inv + b1v.x; o[5] = A[5] * inv + b1v.y;
        o[6] = A[6] * inv + b1v.z; o[7] = A[7] * inv + b1v.w;
        #pragma unroll
        for (int i = 0; i < 8; i++) o[i] = o[i] > 0.f ? o[i] : (expf(o[i]) - 1.f);
        float* op = g_o1 + (long)n * HC + l * 8;
        *(float4*)(op + 0) = make_float4(o[0], o[1], o[2], o[3]);
        *(float4*)(op + 4) = make_float4(o[4], o[5], o[6], o[7]);
    }
}

// ---------------- GEMM2 + fused alpha2 ----------------
__global__ void k_gemm2(const float* __restrict__ W2,
                        const float* __restrict__ a_s, const float* __restrict__ a_d) {
    __shared__ float Ws[HC * NC];
    __shared__ float rows[32 * HC];
    __shared__ float zsm[32 * 41];
    const int t = threadIdx.x;
    const int base = blockIdx.x * 32;
    for (int i = t; i < HC * NC; i += 256) Ws[i] = W2[i];
    for (int i = t; i < 32 * HC; i += 256) {
        int r = i / HC, k = i % HC;
        int gn = base + r;
        rows[i] = (gn < NN) ? g_o1[(long)gn * HC + k] : 0.0f;
    }
    __syncthreads();
    for (int o = t; o < 32 * NC; o += 256) {
        int r = o / NC, c = o % NC;
        int gn = base + r;
        float acc = 0.f;
        const float* rp = rows + r * HC;
        #pragma unroll
        for (int k = 0; k < HC; k++) acc = fmaf(rp[k], Ws[k * NC + c], acc);
        zsm[r * 41 + c] = acc;
        if (gn < NN) g_z[(long)gn * NC + c] = acc;
    }
    __syncthreads();
    if (t < 32) {
        int gn = base + t;
        if (gn < NN) {
            float s = 0.f, d = 0.f;
            #pragma unroll
            for (int c = 0; c < NC; c++) {
                float v = zsm[t * 41 + c];
                s = fmaf(v, a_s[c], s);
                d = fmaf(v, a_d[c], d);
            }
            g_as2[gn] = s;
            g_ad2[gn] = d;
        }
    }
}

// ---------------- layer-2 CSR aggregation + log_softmax: half-warp per edge ----------------
__global__ void k_agg2(float* __restrict__ out, const float* __restrict__ b2) {
    int warp = (blockIdx.x * blockDim.x + threadIdx.x) >> 5;
    if (warp >= NN) return;
    int lane = threadIdx.x & 31;
    int half = lane >> 4;
    int l = lane & 15;
    int n = warp;
    float ad = g_ad2[n];
    int beg = g_row[n], end = g_row[n + 1];
    bool ldz = (l < 10);
    float sp = 0.f;
    float A[4] = {0.f, 0.f, 0.f, 0.f};

    int j = beg + half;
    for (; j + 2 < end; j += 4) {
        int s0 = g_csr[j], s1 = g_csr[j + 2];
        float e0 = g_as2[s0], e1 = g_as2[s1];
        float4 v0 = make_float4(0.f, 0.f, 0.f, 0.f), v1 = v0;
        if (ldz) {
            v0 = *(const float4*)(g_z + (long)s0 * NC + l * 4);
            v1 = *(const float4*)(g_z + (long)s1 * NC + l * 4);
        }
        float p0 = __expf(lrelu(e0 + ad));
        float p1 = __expf(lrelu(e1 + ad));
        sp += p0 + p1;
        A[0] = fmaf(p0, v0.x, A[0]); A[1] = fmaf(p0, v0.y, A[1]);
        A[2] = fmaf(p0, v0.z, A[2]); A[3] = fmaf(p0, v0.w, A[3]);
        A[0] = fmaf(p1, v1.x, A[0]); A[1] = fmaf(p1, v1.y, A[1]);
        A[2] = fmaf(p1, v1.z, A[2]); A[3] = fmaf(p1, v1.w, A[3]);
    }
    for (; j < end; j += 2) {
        int s0 = g_csr[j];
        float e0 = g_as2[s0];
        float4 v0 = make_float4(0.f, 0.f, 0.f, 0.f);
        if (ldz) v0 = *(const float4*)(g_z + (long)s0 * NC + l * 4);
        float p0 = __expf(lrelu(e0 + ad));
        sp += p0;
        A[0] = fmaf(p0, v0.x, A[0]); A[1] = fmaf(p0, v0.y, A[1]);
        A[2] = fmaf(p0, v0.z, A[2]); A[3] = fmaf(p0, v0.w, A[3]);
    }
    #pragma unroll
    for (int i = 0; i < 4; i++) A[i] += __shfl_xor_sync(0xffffffffu, A[i], 16);
    sp += __shfl_xor_sync(0xffffffffu, sp, 16);

    bool act = (half == 0) && ldz;
    float inv = 1.0f / (sp + 1e-16f);
    float v[4];
    float mloc = -3.402823466e38f;
    if (act) {
        float4 bb = *(const float4*)(b2 + l * 4);
        v[0] = A[0] * inv + bb.x; v[1] = A[1] * inv + bb.y;
        v[2] = A[2] * inv + bb.z; v[3] = A[3] * inv + bb.w;
        mloc = fmaxf(fmaxf(v[0], v[1]), fmaxf(v[2], v[3]));
    }
    float m = mloc;
    #pragma unroll
    for (int off = 16; off > 0; off >>= 1)
        m = fmaxf(m, __shfl_xor_sync(0xffffffffu, m, off));
    float sloc = 0.f;
    if (act)
        sloc = expf(v[0] - m) + expf(v[1] - m) + expf(v[2] - m) + expf(v[3] - m);
    float s = sloc;
    #pragma unroll
    for (int off = 16; off > 0; off >>= 1)
        s += __shfl_xor_sync(0xffffffffu, s, off);
    float lse = m + logf(s);
    if (act) {
        float* op = out + (long)n * NC + l * 4;
        *(float4*)op = make_float4(v[0] - lse, v[1] - lse, v[2] - lse, v[3] - lse);
    }
}

// ---------------- launch: fork-join two independent chains ----------------
extern "C" void kernel_launch(void* const* d_in, const int* in_sizes, int n_in,
                              void* d_out, int out_size) {
    const float* x    = (const float*)d_in[0];
    const void*  ei   = d_in[1];
    const float* W1   = (const float*)d_in[2];
    const float* as1  = (const float*)d_in[3];
    const float* ad1  = (const float*)d_in[4];
    const float* b1   = (const float*)d_in[5];
    const float* W2   = (const float*)d_in[6];
    const float* as2  = (const float*)d_in[7];
    const float* ad2  = (const float*)d_in[8];
    const float* b2   = (const float*)d_in[9];
    float*       out  = (float*)d_out;

    static cudaStream_t s2 = 0;
    static cudaEvent_t evFork = 0, evJoin = 0;
    if (s2 == 0) {
        cudaStreamCreateWithFlags(&s2, cudaStreamNonBlocking);
        cudaEventCreateWithFlags(&evFork, cudaEventDisableTiming);
        cudaEventCreateWithFlags(&evJoin, cudaEventDisableTiming);
    }

    const int TB = 256;

    // fork
    cudaEventRecord(evFork, 0);
    cudaStreamWaitEvent(s2, evFork, 0);

    // chain B (side stream): CSR build
    k_init   <<<(NN + TB - 1) / TB, TB, 0, s2>>>(ei);
    k_convert<<<(ETOT + TB - 1) / TB, TB, 0, s2>>>(ei);
    k_scan1  <<<NBLK, 1024, 0, s2>>>();
    k_scan2  <<<1, 32, 0, s2>>>();
    k_scan3  <<<(NN + TB - 1) / TB, TB, 0, s2>>>();
    k_scatter<<<(ETOT + TB - 1) / TB, TB, 0, s2>>>();
    cudaEventRecord(evJoin, s2);

    // chain A (origin stream): dense transform, concurrent with chain B
    k_prepW  <<<(FIN * HC + TB - 1) / TB, TB>>>(W1);
    k_gemm1  <<<(NN + 127) / 128, 256>>>(x, as1, ad1);

    // join
    cudaStreamWaitEvent(0, evJoin, 0);

    // serial tail
    k_agg1   <<<(NN * 32 + TB - 1) / TB, TB>>>(b1);
    k_gemm2  <<<(NN + 31) / 32, 256>>>(W2, as2, ad2);
    k_agg2   <<<(NN * 32 + TB - 1) / TB, TB>>>(out, b2);
}

// round 12
// speedup vs baseline: 1.1543x; 1.0080x over previous
#include <cuda_runtime.h>
#include <cuda_bf16.h>
#include <cuda_fp16.h>
#include <math.h>

#define NN 100000
#define EE 1600000
#define FIN 512
#define H1 8
#define C1 8
#define HC 64
#define NC 40
#define ETOT (EE + NN)
#define NEG_SLOPE 0.2f
#define NBLK 98   // ceil(NN/1024)

// ---------------- scratch ----------------
__device__ unsigned short g_h1h[NN * HC];   // layer-1 features, fp16 (only consumer: agg1)
__device__ float g_as1[NN * H1];
__device__ float g_ad1[NN * H1];
__device__ float g_o1[NN * HC];
__device__ float g_z[NN * NC];
__device__ float g_as2[NN];
__device__ float g_ad2[NN];
__device__ int   g_src[ETOT];
__device__ int   g_dst[ETOT];
__device__ int   g_deg[NN];
__device__ int   g_row[NN + 1];
__device__ int   g_cursor[NN];
__device__ int   g_bsum[NBLK];
__device__ int   g_csr[ETOT];
__device__ int   g_is64 = 1;   // monotone flag, converges identically every call
__device__ unsigned short g_W1T_hi[HC * FIN];
__device__ unsigned short g_W1T_lo[HC * FIN];

__device__ __forceinline__ float lrelu(float x) {
    return x > 0.0f ? x : NEG_SLOPE * x;
}

__device__ __forceinline__ void split_bf16(float v, unsigned short& hi, unsigned short& lo) {
    __nv_bfloat16 h = __float2bfloat16(v);
    float r = v - __bfloat162float(h);
    __nv_bfloat16 l = __float2bfloat16(r);
    hi = __bfloat16_as_ushort(h);
    lo = __bfloat16_as_ushort(l);
}

__device__ __forceinline__ void mma_bf16(float* c, const unsigned* a, const unsigned* b) {
    asm volatile(
        "mma.sync.aligned.m16n8k16.row.col.f32.bf16.bf16.f32 "
        "{%0,%1,%2,%3},{%4,%5,%6,%7},{%8,%9},{%0,%1,%2,%3};"
        : "+f"(c[0]), "+f"(c[1]), "+f"(c[2]), "+f"(c[3])
        : "r"(a[0]), "r"(a[1]), "r"(a[2]), "r"(a[3]), "r"(b[0]), "r"(b[1]));
}

__device__ __forceinline__ void ldsm4(unsigned* r, unsigned addr) {
    asm volatile("ldmatrix.sync.aligned.m8n8.x4.shared.b16 {%0,%1,%2,%3}, [%4];"
                 : "=r"(r[0]), "=r"(r[1]), "=r"(r[2]), "=r"(r[3]) : "r"(addr));
}

// ---------------- init + dtype probe ----------------
__global__ void k_init(const void* __restrict__ ei) {
    int i = blockIdx.x * blockDim.x + threadIdx.x;
    if (i < NN) g_deg[i] = 0;
    if (i < 2048) {
        long long v = ((const long long*)ei)[i];
        if (v < 0 || v >= NN) atomicAnd(&g_is64, 0);
    }
}

// ---------------- edge conversion + degree count ----------------
__global__ void k_convert(const void* __restrict__ ei) {
    int idx = blockIdx.x * blockDim.x + threadIdx.x;
    if (idx >= ETOT) return;
    int s, d;
    if (idx < EE) {
        if (g_is64) {
            const long long* p = (const long long*)ei;
            s = (int)p[idx];
            d = (int)p[EE + idx];
        } else {
            const int* p = (const int*)ei;
            s = p[idx];
            d = p[EE + idx];
        }
    } else {
        s = d = idx - EE;
    }
    s = min(max(s, 0), NN - 1);
    d = min(max(d, 0), NN - 1);
    g_src[idx] = s;
    g_dst[idx] = d;
    atomicAdd(&g_deg[d], 1);
}

// ---------------- exclusive scan of degrees ----------------
__global__ void k_scan1() {
    __shared__ int sh[1024];
    int tid = threadIdx.x;
    int i = blockIdx.x * 1024 + tid;
    int v = (i < NN) ? g_deg[i] : 0;
    sh[tid] = v;
    __syncthreads();
    #pragma unroll
    for (int off = 1; off < 1024; off <<= 1) {
        int t = (tid >= off) ? sh[tid - off] : 0;
        __syncthreads();
        sh[tid] += t;
        __syncthreads();
    }
    if (i < NN) g_row[i] = sh[tid] - v;
    if (tid == 1023) g_bsum[blockIdx.x] = sh[1023];
}

__global__ void k_scan2() {
    if (threadIdx.x == 0) {
        int acc = 0;
        for (int b = 0; b < NBLK; b++) { int t = g_bsum[b]; g_bsum[b] = acc; acc += t; }
        g_row[NN] = acc;
    }
}

__global__ void k_scan3() {
    int i = blockIdx.x * blockDim.x + threadIdx.x;
    if (i < NN) {
        int r = g_row[i] + g_bsum[i >> 10];
        g_row[i] = r;
        g_cursor[i] = r;
    }
}

__global__ void k_scatter() {
    int idx = blockIdx.x * blockDim.x + threadIdx.x;
    if (idx >= ETOT) return;
    int d = g_dst[idx];
    int pos = atomicAdd(&g_cursor[d], 1);
    g_csr[pos] = g_src[idx];
}

// ---------------- W1 split/transpose ----------------
__global__ void k_prepW(const float* __restrict__ W1) {
    int i = blockIdx.x * blockDim.x + threadIdx.x;
    if (i >= FIN * HC) return;
    int k = i / HC, n = i % HC;
    unsigned short hi, lo;
    split_bf16(W1[i], hi, lo);
    g_W1T_hi[n * FIN + k] = hi;
    g_W1T_lo[n * FIN + k] = lo;
}

// ---------------- GEMM1 (bf16x3 tensor cores, ldmatrix fragments) + fused alpha1 ----------------
#define ASTR 40
__global__ __launch_bounds__(256) void k_gemm1(const float* __restrict__ x,
                                               const float* __restrict__ a_s,
                                               const float* __restrict__ a_d) {
    __shared__ __align__(16) unsigned short As_hi[128 * ASTR];
    __shared__ __align__(16) unsigned short As_lo[128 * ASTR];
    __shared__ __align__(16) unsigned short Bs_hi[64 * ASTR];
    __shared__ __align__(16) unsigned short Bs_lo[64 * ASTR];

    const int t = threadIdx.x;
    const int bm0 = blockIdx.x * 128;
    const int warp = t >> 5;
    const int lane = t & 31;
    const int g = lane >> 2;
    const int q = lane & 3;
    const int warp_m = warp >> 1;
    const int warp_n = warp & 1;

    const int mat = lane >> 3;
    const int rowin = lane & 7;
    const int lm_off = ((mat & 1) * 8 + rowin) * ASTR + (mat >> 1) * 8;  // elements

    const unsigned ash = (unsigned)__cvta_generic_to_shared(As_hi);
    const unsigned asl = (unsigned)__cvta_generic_to_shared(As_lo);
    const unsigned bsh = (unsigned)__cvta_generic_to_shared(Bs_hi);
    const unsigned bsl = (unsigned)__cvta_generic_to_shared(Bs_lo);

    float acc[2][4][4];
    #pragma unroll
    for (int i = 0; i < 2; i++)
        #pragma unroll
        for (int j = 0; j < 4; j++)
            #pragma unroll
            for (int r = 0; r < 4; r++) acc[i][j][r] = 0.f;

    for (int k0 = 0; k0 < FIN; k0 += 32) {
        #pragma unroll
        for (int i = 0; i < 4; i++) {
            int idx = i * 256 + t;
            int row = idx >> 3;
            int col = (idx & 7) * 4;
            float4 v = make_float4(0.f, 0.f, 0.f, 0.f);
            int gr = bm0 + row;
            if (gr < NN) v = *(const float4*)(x + (long)gr * FIN + k0 + col);
            unsigned short h0, l0, h1_, l1_, h2, l2, h3, l3;
            split_bf16(v.x, h0, l0);
            split_bf16(v.y, h1_, l1_);
            split_bf16(v.z, h2, l2);
            split_bf16(v.w, h3, l3);
            unsigned* ph = (unsigned*)&As_hi[row * ASTR + col];
            unsigned* pl = (unsigned*)&As_lo[row * ASTR + col];
            ph[0] = (unsigned)h0 | ((unsigned)h1_ << 16);
            ph[1] = (unsigned)h2 | ((unsigned)h3 << 16);
            pl[0] = (unsigned)l0 | ((unsigned)l1_ << 16);
            pl[1] = (unsigned)l2 | ((unsigned)l3 << 16);
        }
        {
            int row = t >> 2;
            int seg = t & 3;
            uint4 vh = *(const uint4*)&g_W1T_hi[row * FIN + k0 + seg * 8];
            uint4 vl = *(const uint4*)&g_W1T_lo[row * FIN + k0 + seg * 8];
            *(uint4*)&Bs_hi[row * ASTR + seg * 8] = vh;
            *(uint4*)&Bs_lo[row * ASTR + seg * 8] = vl;
        }
        __syncthreads();

        #pragma unroll
        for (int ka = 0; ka < 2; ka++) {
            const int kc = ka * 16;
            unsigned a_hi[2][4], a_lo[2][4], b_hi[4][2], b_lo[4][2];
            #pragma unroll
            for (int ma = 0; ma < 2; ma++) {
                int r0 = warp_m * 32 + ma * 16;
                unsigned eoff = (unsigned)((r0 * ASTR + kc + lm_off) * 2);
                ldsm4(a_hi[ma], ash + eoff);
                ldsm4(a_lo[ma], asl + eoff);
            }
            #pragma unroll
            for (int p = 0; p < 2; p++) {
                int n0 = warp_n * 32 + p * 16;
                unsigned eoff = (unsigned)((n0 * ASTR + kc + lm_off) * 2);
                unsigned rh[4], rl[4];
                ldsm4(rh, bsh + eoff);
                ldsm4(rl, bsl + eoff);
                b_hi[2 * p][0] = rh[0]; b_hi[2 * p][1] = rh[2];
                b_hi[2 * p + 1][0] = rh[1]; b_hi[2 * p + 1][1] = rh[3];
                b_lo[2 * p][0] = rl[0]; b_lo[2 * p][1] = rl[2];
                b_lo[2 * p + 1][0] = rl[1]; b_lo[2 * p + 1][1] = rl[3];
            }
            #pragma unroll
            for (int ma = 0; ma < 2; ma++)
                #pragma unroll
                for (int na = 0; na < 4; na++) {
                    mma_bf16(acc[ma][na], a_hi[ma], b_hi[na]);
                    mma_bf16(acc[ma][na], a_hi[ma], b_lo[na]);
                    mma_bf16(acc[ma][na], a_lo[ma], b_hi[na]);
                }
        }
        __syncthreads();
    }

    // ---- epilogue: write h1 as fp16 (half2 per 4 bytes) ----
    #pragma unroll
    for (int ma = 0; ma < 2; ma++) {
        int r0 = bm0 + warp_m * 32 + ma * 16 + g;
        #pragma unroll
        for (int na = 0; na < 4; na++) {
            int c = warp_n * 32 + na * 8 + 2 * q;
            if (r0 < NN)
                *(__half2*)(g_h1h + (long)r0 * HC + c) =
                    __floats2half2_rn(acc[ma][na][0], acc[ma][na][1]);
            if (r0 + 8 < NN)
                *(__half2*)(g_h1h + (long)(r0 + 8) * HC + c) =
                    __floats2half2_rn(acc[ma][na][2], acc[ma][na][3]);
        }
    }

    // ---- fused alpha1 (full fp32 accumulators) ----
    float as_c0[4], as_c1[4], ad_c0[4], ad_c1[4];
    #pragma unroll
    for (int na = 0; na < 4; na++) {
        int hh = warp_n * 4 + na;
        as_c0[na] = a_s[hh * 8 + 2 * q];
        as_c1[na] = a_s[hh * 8 + 2 * q + 1];
        ad_c0[na] = a_d[hh * 8 + 2 * q];
        ad_c1[na] = a_d[hh * 8 + 2 * q + 1];
    }
    #pragma unroll
    for (int ma = 0; ma < 2; ma++)
        #pragma unroll
        for (int rh = 0; rh < 2; rh++) {
            float s[4], d[4];
            #pragma unroll
            for (int na = 0; na < 4; na++) {
                float h0 = acc[ma][na][rh * 2 + 0];
                float h1v = acc[ma][na][rh * 2 + 1];
                s[na] = h0 * as_c0[na] + h1v * as_c1[na];
                d[na] = h0 * ad_c0[na] + h1v * ad_c1[na];
            }
            #pragma unroll
            for (int na = 0; na < 4; na++) {
                s[na] += __shfl_xor_sync(0xffffffffu, s[na], 1);
                s[na] += __shfl_xor_sync(0xffffffffu, s[na], 2);
                d[na] += __shfl_xor_sync(0xffffffffu, d[na], 1);
                d[na] += __shfl_xor_sync(0xffffffffu, d[na], 2);
            }
            int row = bm0 + warp_m * 32 + ma * 16 + rh * 8 + g;
            if (q == 0 && row < NN) {
                *(float4*)(g_as1 + row * H1 + warp_n * 4) = make_float4(s[0], s[1], s[2], s[3]);
                *(float4*)(g_ad1 + row * H1 + warp_n * 4) = make_float4(d[0], d[1], d[2], d[3]);
            }
        }
}

// ---------------- layer-1 CSR aggregation: quarter-warp per edge, fp16 rows ----------------
__global__ void k_agg1(const float* __restrict__ b1) {
    int warp = (blockIdx.x * blockDim.x + threadIdx.x) >> 5;
    if (warp >= NN) return;
    int lane = threadIdx.x & 31;
    int qt = lane >> 3;
    int l = lane & 7;
    int n = warp;
    float adh = g_ad1[n * H1 + l];
    int beg = g_row[n], end = g_row[n + 1];
    float sp = 0.f;
    float A[8] = {0.f, 0.f, 0.f, 0.f, 0.f, 0.f, 0.f, 0.f};

    int j = beg + qt;
    for (; j + 4 < end; j += 8) {
        int s0 = g_csr[j], s1 = g_csr[j + 4];
        float e0 = g_as1[s0 * H1 + l];
        float e1 = g_as1[s1 * H1 + l];
        uint4 u0 = *(const uint4*)(g_h1h + (long)s0 * HC + l * 8);  // 8 halves
        uint4 u1 = *(const uint4*)(g_h1h + (long)s1 * HC + l * 8);
        float p0 = __expf(lrelu(e0 + adh));
        float p1 = __expf(lrelu(e1 + adh));
        sp += p0 + p1;
        const __half2* hp0 = (const __half2*)&u0;
        const __half2* hp1 = (const __half2*)&u1;
        #pragma unroll
        for (int w = 0; w < 4; w++) {
            float2 f0 = __half22float2(hp0[w]);
            float2 f1 = __half22float2(hp1[w]);
            A[2 * w + 0] = fmaf(p0, f0.x, A[2 * w + 0]);
            A[2 * w + 1] = fmaf(p0, f0.y, A[2 * w + 1]);
            A[2 * w + 0] = fmaf(p1, f1.x, A[2 * w + 0]);
            A[2 * w + 1] = fmaf(p1, f1.y, A[2 * w + 1]);
        }
    }
    for (; j < end; j += 4) {
        int s0 = g_csr[j];
        float e0 = g_as1[s0 * H1 + l];
        uint4 u0 = *(const uint4*)(g_h1h + (long)s0 * HC + l * 8);
        float p0 = __expf(lrelu(e0 + adh));
        sp += p0;
        const __half2* hp0 = (const __half2*)&u0;
        #pragma unroll
        for (int w = 0; w < 4; w++) {
            float2 f0 = __half22float2(hp0[w]);
            A[2 * w + 0] = fmaf(p0, f0.x, A[2 * w + 0]);
            A[2 * w + 1] = fmaf(p0, f0.y, A[2 * w + 1]);
        }
    }
    #pragma unroll
    for (int i = 0; i < 8; i++) {
        A[i] += __shfl_xor_sync(0xffffffffu, A[i], 8);
        A[i] += __shfl_xor_sync(0xffffffffu, A[i], 16);
    }
    sp += __shfl_xor_sync(0xffffffffu, sp, 8);
    sp += __shfl_xor_sync(0xffffffffu, sp, 16);

    if (qt == 0) {
        float inv = 1.0f / (sp + 1e-16f);
        float4 b0 = *(const float4*)(b1 + l * 8);
        float4 b1v = *(const float4*)(b1 + l * 8 + 4);
        float o[8];
        o[0] = A[0] * inv + b0.x; o[1] = A[1] * inv + b0.y;
        o[2] = A[2] * inv + b0.z; o[3] = A[3] * inv + b0.w;
        o[4] = A[4] * inv + b1v.x; o[5] = A[5] * inv + b1v.y;
        o[6] = A[6] * inv + b1v.z; o[7] = A[7] * inv + b1v.w;
        #pragma unroll
        for (int i = 0; i < 8; i++) o[i] = o[i] > 0.f ? o[i] : (expf(o[i]) - 1.f);
        float* op = g_o1 + (long)n * HC + l * 8;
        *(float4*)(op + 0) = make_float4(o[0], o[1], o[2], o[3]);
        *(float4*)(op + 4) = make_float4(o[4], o[5], o[6], o[7]);
    }
}

// ---------------- GEMM2 + fused alpha2 ----------------
__global__ void k_gemm2(const float* __restrict__ W2,
                        const float* __restrict__ a_s, const float* __restrict__ a_d) {
    __shared__ float Ws[HC * NC];
    __shared__ float rows[32 * HC];
    __shared__ float zsm[32 * 41];
    const int t = threadIdx.x;
    const int base = blockIdx.x * 32;
    for (int i = t; i < HC * NC; i += 256) Ws[i] = W2[i];
    for (int i = t; i < 32 * HC; i += 256) {
        int r = i / HC, k = i % HC;
        int gn = base + r;
        rows[i] = (gn < NN) ? g_o1[(long)gn * HC + k] : 0.0f;
    }
    __syncthreads();
    for (int o = t; o < 32 * NC; o += 256) {
        int r = o / NC, c = o % NC;
        int gn = base + r;
        float acc = 0.f;
        const float* rp = rows + r * HC;
        #pragma unroll
        for (int k = 0; k < HC; k++) acc = fmaf(rp[k], Ws[k * NC + c], acc);
        zsm[r * 41 + c] = acc;
        if (gn < NN) g_z[(long)gn * NC + c] = acc;
    }
    __syncthreads();
    if (t < 32) {
        int gn = base + t;
        if (gn < NN) {
            float s = 0.f, d = 0.f;
            #pragma unroll
            for (int c = 0; c < NC; c++) {
                float v = zsm[t * 41 + c];
                s = fmaf(v, a_s[c], s);
                d = fmaf(v, a_d[c], d);
            }
            g_as2[gn] = s;
            g_ad2[gn] = d;
        }
    }
}

// ---------------- layer-2 CSR aggregation + log_softmax: half-warp per edge ----------------
__global__ void k_agg2(float* __restrict__ out, const float* __restrict__ b2) {
    int warp = (blockIdx.x * blockDim.x + threadIdx.x) >> 5;
    if (warp >= NN) return;
    int lane = threadIdx.x & 31;
    int half = lane >> 4;
    int l = lane & 15;
    int n = warp;
    float ad = g_ad2[n];
    int beg = g_row[n], end = g_row[n + 1];
    bool ldz = (l < 10);
    float sp = 0.f;
    float A[4] = {0.f, 0.f, 0.f, 0.f};

    int j = beg + half;
    for (; j + 2 < end; j += 4) {
        int s0 = g_csr[j], s1 = g_csr[j + 2];
        float e0 = g_as2[s0], e1 = g_as2[s1];
        float4 v0 = make_float4(0.f, 0.f, 0.f, 0.f), v1 = v0;
        if (ldz) {
            v0 = *(const float4*)(g_z + (long)s0 * NC + l * 4);
            v1 = *(const float4*)(g_z + (long)s1 * NC + l * 4);
        }
        float p0 = __expf(lrelu(e0 + ad));
        float p1 = __expf(lrelu(e1 + ad));
        sp += p0 + p1;
        A[0] = fmaf(p0, v0.x, A[0]); A[1] = fmaf(p0, v0.y, A[1]);
        A[2] = fmaf(p0, v0.z, A[2]); A[3] = fmaf(p0, v0.w, A[3]);
        A[0] = fmaf(p1, v1.x, A[0]); A[1] = fmaf(p1, v1.y, A[1]);
        A[2] = fmaf(p1, v1.z, A[2]); A[3] = fmaf(p1, v1.w, A[3]);
    }
    for (; j < end; j += 2) {
        int s0 = g_csr[j];
        float e0 = g_as2[s0];
        float4 v0 = make_float4(0.f, 0.f, 0.f, 0.f);
        if (ldz) v0 = *(const float4*)(g_z + (long)s0 * NC + l * 4);
        float p0 = __expf(lrelu(e0 + ad));
        sp += p0;
        A[0] = fmaf(p0, v0.x, A[0]); A[1] = fmaf(p0, v0.y, A[1]);
        A[2] = fmaf(p0, v0.z, A[2]); A[3] = fmaf(p0, v0.w, A[3]);
    }
    #pragma unroll
    for (int i = 0; i < 4; i++) A[i] += __shfl_xor_sync(0xffffffffu, A[i], 16);
    sp += __shfl_xor_sync(0xffffffffu, sp, 16);

    bool act = (half == 0) && ldz;
    float inv = 1.0f / (sp + 1e-16f);
    float v[4];
    float mloc = -3.402823466e38f;
    if (act) {
        float4 bb = *(const float4*)(b2 + l * 4);
        v[0] = A[0] * inv + bb.x; v[1] = A[1] * inv + bb.y;
        v[2] = A[2] * inv + bb.z; v[3] = A[3] * inv + bb.w;
        mloc = fmaxf(fmaxf(v[0], v[1]), fmaxf(v[2], v[3]));
    }
    float m = mloc;
    #pragma unroll
    for (int off = 16; off > 0; off >>= 1)
        m = fmaxf(m, __shfl_xor_sync(0xffffffffu, m, off));
    float sloc = 0.f;
    if (act)
        sloc = expf(v[0] - m) + expf(v[1] - m) + expf(v[2] - m) + expf(v[3] - m);
    float s = sloc;
    #pragma unroll
    for (int off = 16; off > 0; off >>= 1)
        s += __shfl_xor_sync(0xffffffffu, s, off);
    float lse = m + logf(s);
    if (act) {
        float* op = out + (long)n * NC + l * 4;
        *(float4*)op = make_float4(v[0] - lse, v[1] - lse, v[2] - lse, v[3] - lse);
    }
}

// ---------------- launch: fork-join two independent chains ----------------
extern "C" void kernel_launch(void* const* d_in, const int* in_sizes, int n_in,
                              void* d_out, int out_size) {
    const float* x    = (const float*)d_in[0];
    const void*  ei   = d_in[1];
    const float* W1   = (const float*)d_in[2];
    const float* as1  = (const float*)d_in[3];
    const float* ad1  = (const float*)d_in[4];
    const float* b1   = (const float*)d_in[5];
    const float* W2   = (const float*)d_in[6];
    const float* as2  = (const float*)d_in[7];
    const float* ad2  = (const float*)d_in[8];
    const float* b2   = (const float*)d_in[9];
    float*       out  = (float*)d_out;

    static cudaStream_t s2 = 0;
    static cudaEvent_t evFork = 0, evJoin = 0;
    if (s2 == 0) {
        cudaStreamCreateWithFlags(&s2, cudaStreamNonBlocking);
        cudaEventCreateWithFlags(&evFork, cudaEventDisableTiming);
        cudaEventCreateWithFlags(&evJoin, cudaEventDisableTiming);
    }

    const int TB = 256;

    // fork
    cudaEventRecord(evFork, 0);
    cudaStreamWaitEvent(s2, evFork, 0);

    // chain B (side stream): CSR build
    k_init   <<<(NN + TB - 1) / TB, TB, 0, s2>>>(ei);
    k_convert<<<(ETOT + TB - 1) / TB, TB, 0, s2>>>(ei);
    k_scan1  <<<NBLK, 1024, 0, s2>>>();
    k_scan2  <<<1, 32, 0, s2>>>();
    k_scan3  <<<(NN + TB - 1) / TB, TB, 0, s2>>>();
    k_scatter<<<(ETOT + TB - 1) / TB, TB, 0, s2>>>();
    cudaEventRecord(evJoin, s2);

    // chain A (origin stream): dense transform, concurrent with chain B
    k_prepW  <<<(FIN * HC + TB - 1) / TB, TB>>>(W1);
    k_gemm1  <<<(NN + 127) / 128, 256>>>(x, as1, ad1);

    // join
    cudaStreamWaitEvent(0, evJoin, 0);

    // serial tail
    k_agg1   <<<(NN * 32 + TB - 1) / TB, TB>>>(b1);
    k_gemm2  <<<(NN + 31) / 32, 256>>>(W2, as2, ad2);
    k_agg2   <<<(NN * 32 + TB - 1) / TB, TB>>>(out, b2);
}

// round 13
// speedup vs baseline: 1.1812x; 1.0233x over previous
#include <cuda_runtime.h>
#include <cuda_bf16.h>
#include <cuda_fp16.h>
#include <math.h>

#define NN 100000
#define EE 1600000
#define FIN 512
#define H1 8
#define C1 8
#define HC 64
#define NC 40
#define ETOT (EE + NN)
#define NEG_SLOPE 0.2f
#define NBLK 98   // ceil(NN/1024)

// ---------------- scratch ----------------
__device__ unsigned short g_h1h[NN * HC];   // layer-1 features, fp16 (only consumer: agg1)
__device__ float g_as1[NN * H1];
__device__ float g_ad1[NN * H1];
__device__ float g_o1[NN * HC];
__device__ float g_z[NN * NC];
__device__ float g_as2[NN];
__device__ float g_ad2[NN];
__device__ int   g_src[ETOT];
__device__ int   g_dst[ETOT];
__device__ int   g_deg[NN];
__device__ int   g_row[NN + 1];
__device__ int   g_cursor[NN];
__device__ int   g_bsum[NBLK];
__device__ int   g_csr[ETOT];
__device__ int   g_is64 = 1;   // monotone flag, converges identically every call
__device__ unsigned short g_W1T_hi[HC * FIN];
__device__ unsigned short g_W1T_lo[HC * FIN];

__device__ __forceinline__ float lrelu(float x) {
    return x > 0.0f ? x : NEG_SLOPE * x;
}

__device__ __forceinline__ void split_bf16(float v, unsigned short& hi, unsigned short& lo) {
    __nv_bfloat16 h = __float2bfloat16(v);
    float r = v - __bfloat162float(h);
    __nv_bfloat16 l = __float2bfloat16(r);
    hi = __bfloat16_as_ushort(h);
    lo = __bfloat16_as_ushort(l);
}

__device__ __forceinline__ void mma_bf16(float* c, const unsigned* a, const unsigned* b) {
    asm volatile(
        "mma.sync.aligned.m16n8k16.row.col.f32.bf16.bf16.f32 "
        "{%0,%1,%2,%3},{%4,%5,%6,%7},{%8,%9},{%0,%1,%2,%3};"
        : "+f"(c[0]), "+f"(c[1]), "+f"(c[2]), "+f"(c[3])
        : "r"(a[0]), "r"(a[1]), "r"(a[2]), "r"(a[3]), "r"(b[0]), "r"(b[1]));
}

__device__ __forceinline__ void ldsm4(unsigned* r, unsigned addr) {
    asm volatile("ldmatrix.sync.aligned.m8n8.x4.shared.b16 {%0,%1,%2,%3}, [%4];"
                 : "=r"(r[0]), "=r"(r[1]), "=r"(r[2]), "=r"(r[3]) : "r"(addr));
}

// ---------------- init + dtype probe ----------------
__global__ void k_init(const void* __restrict__ ei) {
    int i = blockIdx.x * blockDim.x + threadIdx.x;
    if (i < NN) g_deg[i] = 0;
    if (i < 2048) {
        long long v = ((const long long*)ei)[i];
        if (v < 0 || v >= NN) atomicAnd(&g_is64, 0);
    }
}

// ---------------- edge conversion + degree count ----------------
__global__ void k_convert(const void* __restrict__ ei) {
    int idx = blockIdx.x * blockDim.x + threadIdx.x;
    if (idx >= ETOT) return;
    int s, d;
    if (idx < EE) {
        if (g_is64) {
            const long long* p = (const long long*)ei;
            s = (int)p[idx];
            d = (int)p[EE + idx];
        } else {
            const int* p = (const int*)ei;
            s = p[idx];
            d = p[EE + idx];
        }
    } else {
        s = d = idx - EE;
    }
    s = min(max(s, 0), NN - 1);
    d = min(max(d, 0), NN - 1);
    g_src[idx] = s;
    g_dst[idx] = d;
    atomicAdd(&g_deg[d], 1);
}

// ---------------- exclusive scan of degrees ----------------
__global__ void k_scan1() {
    __shared__ int sh[1024];
    int tid = threadIdx.x;
    int i = blockIdx.x * 1024 + tid;
    int v = (i < NN) ? g_deg[i] : 0;
    sh[tid] = v;
    __syncthreads();
    #pragma unroll
    for (int off = 1; off < 1024; off <<= 1) {
        int t = (tid >= off) ? sh[tid - off] : 0;
        __syncthreads();
        sh[tid] += t;
        __syncthreads();
    }
    if (i < NN) g_row[i] = sh[tid] - v;
    if (tid == 1023) g_bsum[blockIdx.x] = sh[1023];
}

__global__ void k_scan2() {
    if (threadIdx.x == 0) {
        int acc = 0;
        for (int b = 0; b < NBLK; b++) { int t = g_bsum[b]; g_bsum[b] = acc; acc += t; }
        g_row[NN] = acc;
    }
}

__global__ void k_scan3() {
    int i = blockIdx.x * blockDim.x + threadIdx.x;
    if (i < NN) {
        int r = g_row[i] + g_bsum[i >> 10];
        g_row[i] = r;
        g_cursor[i] = r;
    }
}

__global__ void k_scatter() {
    int idx = blockIdx.x * blockDim.x + threadIdx.x;
    if (idx >= ETOT) return;
    int d = g_dst[idx];
    int pos = atomicAdd(&g_cursor[d], 1);
    g_csr[pos] = g_src[idx];
}

// ---------------- W1 split/transpose ----------------
__global__ void k_prepW(const float* __restrict__ W1) {
    int i = blockIdx.x * blockDim.x + threadIdx.x;
    if (i >= FIN * HC) return;
    int k = i / HC, n = i % HC;
    unsigned short hi, lo;
    split_bf16(W1[i], hi, lo);
    g_W1T_hi[n * FIN + k] = hi;
    g_W1T_lo[n * FIN + k] = lo;
}

// ---------------- GEMM1: bf16x3 tensor cores, ldmatrix, ping-pong pipeline ----------------
#define ASTR 40
#define ABYT (128 * ASTR * 2)   // 10240 B per A buffer
#define BBYT (64 * ASTR * 2)    // 5120 B per B buffer
#define OFF_AH(b) ((b) * ABYT)
#define OFF_AL(b) (2 * ABYT + (b) * ABYT)
#define OFF_BH(b) (4 * ABYT + (b) * BBYT)
#define OFF_BL(b) (4 * ABYT + 2 * BBYT + (b) * BBYT)
#define SMEM_G1  (4 * ABYT + 4 * BBYT)   // 61440 B

__global__ __launch_bounds__(256, 2) void k_gemm1(const float* __restrict__ x,
                                                  const float* __restrict__ a_s,
                                                  const float* __restrict__ a_d) {
    extern __shared__ __align__(16) char sm[];
    const unsigned smu = (unsigned)__cvta_generic_to_shared(sm);

    const int t = threadIdx.x;
    const int bm0 = blockIdx.x * 128;
    const int warp = t >> 5;
    const int lane = t & 31;
    const int g = lane >> 2;
    const int q = lane & 3;
    const int warp_m = warp >> 1;
    const int warp_n = warp & 1;
    const int brow = t >> 2;
    const int bseg = t & 3;

    // ldmatrix lane offset
    const int mat = lane >> 3;
    const int rowin = lane & 7;
    const int lm_off = ((mat & 1) * 8 + rowin) * ASTR + (mat >> 1) * 8;  // elements

    float acc[2][4][4];
    #pragma unroll
    for (int i = 0; i < 2; i++)
        #pragma unroll
        for (int j = 0; j < 4; j++)
            #pragma unroll
            for (int r = 0; r < 4; r++) acc[i][j][r] = 0.f;

    float4 ra[4];
    uint4 rbh, rbl;

    auto load_regs = [&](int k0) {
        #pragma unroll
        for (int i = 0; i < 4; i++) {
            int idx = i * 256 + t;
            int row = idx >> 3;
            int col = (idx & 7) * 4;
            int gr = bm0 + row;
            ra[i] = (gr < NN) ? *(const float4*)(x + (long)gr * FIN + k0 + col)
                              : make_float4(0.f, 0.f, 0.f, 0.f);
        }
        rbh = *(const uint4*)&g_W1T_hi[brow * FIN + k0 + bseg * 8];
        rbl = *(const uint4*)&g_W1T_lo[brow * FIN + k0 + bseg * 8];
    };

    auto store_smem = [&](int b) {
        unsigned short* AsH = (unsigned short*)(sm + OFF_AH(b));
        unsigned short* AsL = (unsigned short*)(sm + OFF_AL(b));
        unsigned short* BsH = (unsigned short*)(sm + OFF_BH(b));
        unsigned short* BsL = (unsigned short*)(sm + OFF_BL(b));
        #pragma unroll
        for (int i = 0; i < 4; i++) {
            int idx = i * 256 + t;
            int row = idx >> 3;
            int col = (idx & 7) * 4;
            unsigned short h0, l0, h1_, l1_, h2, l2, h3, l3;
            split_bf16(ra[i].x, h0, l0);
            split_bf16(ra[i].y, h1_, l1_);
            split_bf16(ra[i].z, h2, l2);
            split_bf16(ra[i].w, h3, l3);
            unsigned* ph = (unsigned*)&AsH[row * ASTR + col];
            unsigned* pl = (unsigned*)&AsL[row * ASTR + col];
            ph[0] = (unsigned)h0 | ((unsigned)h1_ << 16);
            ph[1] = (unsigned)h2 | ((unsigned)h3 << 16);
            pl[0] = (unsigned)l0 | ((unsigned)l1_ << 16);
            pl[1] = (unsigned)l2 | ((unsigned)l3 << 16);
        }
        *(uint4*)&BsH[brow * ASTR + bseg * 8] = rbh;
        *(uint4*)&BsL[brow * ASTR + bseg * 8] = rbl;
    };

    // prologue
    load_regs(0);
    store_smem(0);

    for (int kt = 0; kt < FIN / 32; kt++) {
        const int cur = kt & 1;
        __syncthreads();
        if (kt + 1 < FIN / 32) load_regs((kt + 1) * 32);

        const unsigned ash = smu + OFF_AH(cur);
        const unsigned asl = smu + OFF_AL(cur);
        const unsigned bsh = smu + OFF_BH(cur);
        const unsigned bsl = smu + OFF_BL(cur);

        #pragma unroll
        for (int ka = 0; ka < 2; ka++) {
            const int kc = ka * 16;
            unsigned a_hi[2][4], a_lo[2][4], b_hi[4][2], b_lo[4][2];
            #pragma unroll
            for (int ma = 0; ma < 2; ma++) {
                int r0 = warp_m * 32 + ma * 16;
                unsigned eoff = (unsigned)((r0 * ASTR + kc + lm_off) * 2);
                ldsm4(a_hi[ma], ash + eoff);
                ldsm4(a_lo[ma], asl + eoff);
            }
            // B: r0 = n0-7/k0-7, r1 = n8-15/k0-7, r2 = n0-7/k8-15, r3 = n8-15/k8-15
            #pragma unroll
            for (int p = 0; p < 2; p++) {
                int n0 = warp_n * 32 + p * 16;
                unsigned eoff = (unsigned)((n0 * ASTR + kc + lm_off) * 2);
                unsigned rh[4], rl[4];
                ldsm4(rh, bsh + eoff);
                ldsm4(rl, bsl + eoff);
                b_hi[2 * p][0] = rh[0]; b_hi[2 * p][1] = rh[2];
                b_hi[2 * p + 1][0] = rh[1]; b_hi[2 * p + 1][1] = rh[3];
                b_lo[2 * p][0] = rl[0]; b_lo[2 * p][1] = rl[2];
                b_lo[2 * p + 1][0] = rl[1]; b_lo[2 * p + 1][1] = rl[3];
            }
            #pragma unroll
            for (int ma = 0; ma < 2; ma++)
                #pragma unroll
                for (int na = 0; na < 4; na++) {
                    mma_bf16(acc[ma][na], a_hi[ma], b_hi[na]);
                    mma_bf16(acc[ma][na], a_hi[ma], b_lo[na]);
                    mma_bf16(acc[ma][na], a_lo[ma], b_hi[na]);
                }
        }

        if (kt + 1 < FIN / 32) store_smem(cur ^ 1);
    }

    // ---- epilogue: write h1 as fp16 ----
    #pragma unroll
    for (int ma = 0; ma < 2; ma++) {
        int r0 = bm0 + warp_m * 32 + ma * 16 + g;
        #pragma unroll
        for (int na = 0; na < 4; na++) {
            int c = warp_n * 32 + na * 8 + 2 * q;
            if (r0 < NN)
                *(__half2*)(g_h1h + (long)r0 * HC + c) =
                    __floats2half2_rn(acc[ma][na][0], acc[ma][na][1]);
            if (r0 + 8 < NN)
                *(__half2*)(g_h1h + (long)(r0 + 8) * HC + c) =
                    __floats2half2_rn(acc[ma][na][2], acc[ma][na][3]);
        }
    }

    // ---- fused alpha1 ----
    float as_c0[4], as_c1[4], ad_c0[4], ad_c1[4];
    #pragma unroll
    for (int na = 0; na < 4; na++) {
        int hh = warp_n * 4 + na;
        as_c0[na] = a_s[hh * 8 + 2 * q];
        as_c1[na] = a_s[hh * 8 + 2 * q + 1];
        ad_c0[na] = a_d[hh * 8 + 2 * q];
        ad_c1[na] = a_d[hh * 8 + 2 * q + 1];
    }
    #pragma unroll
    for (int ma = 0; ma < 2; ma++)
        #pragma unroll
        for (int rh = 0; rh < 2; rh++) {
            float s[4], d[4];
            #pragma unroll
            for (int na = 0; na < 4; na++) {
                float h0 = acc[ma][na][rh * 2 + 0];
                float h1v = acc[ma][na][rh * 2 + 1];
                s[na] = h0 * as_c0[na] + h1v * as_c1[na];
                d[na] = h0 * ad_c0[na] + h1v * ad_c1[na];
            }
            #pragma unroll
            for (int na = 0; na < 4; na++) {
                s[na] += __shfl_xor_sync(0xffffffffu, s[na], 1);
                s[na] += __shfl_xor_sync(0xffffffffu, s[na], 2);
                d[na] += __shfl_xor_sync(0xffffffffu, d[na], 1);
                d[na] += __shfl_xor_sync(0xffffffffu, d[na], 2);
            }
            int row = bm0 + warp_m * 32 + ma * 16 + rh * 8 + g;
            if (q == 0 && row < NN) {
                *(float4*)(g_as1 + row * H1 + warp_n * 4) = make_float4(s[0], s[1], s[2], s[3]);
                *(float4*)(g_ad1 + row * H1 + warp_n * 4) = make_float4(d[0], d[1], d[2], d[3]);
            }
        }
}

// ---------------- layer-1 CSR aggregation: quarter-warp per edge, fp16 rows ----------------
__global__ void k_agg1(const float* __restrict__ b1) {
    int warp = (blockIdx.x * blockDim.x + threadIdx.x) >> 5;
    if (warp >= NN) return;
    int lane = threadIdx.x & 31;
    int qt = lane >> 3;
    int l = lane & 7;
    int n = warp;
    float adh = g_ad1[n * H1 + l];
    int beg = g_row[n], end = g_row[n + 1];
    float sp = 0.f;
    float A[8] = {0.f, 0.f, 0.f, 0.f, 0.f, 0.f, 0.f, 0.f};

    int j = beg + qt;
    for (; j + 4 < end; j += 8) {
        int s0 = g_csr[j], s1 = g_csr[j + 4];
        float e0 = g_as1[s0 * H1 + l];
        float e1 = g_as1[s1 * H1 + l];
        uint4 u0 = *(const uint4*)(g_h1h + (long)s0 * HC + l * 8);  // 8 halves
        uint4 u1 = *(const uint4*)(g_h1h + (long)s1 * HC + l * 8);
        float p0 = __expf(lrelu(e0 + adh));
        float p1 = __expf(lrelu(e1 + adh));
        sp += p0 + p1;
        const __half2* hp0 = (const __half2*)&u0;
        const __half2* hp1 = (const __half2*)&u1;
        #pragma unroll
        for (int w = 0; w < 4; w++) {
            float2 f0 = __half22float2(hp0[w]);
            float2 f1 = __half22float2(hp1[w]);
            A[2 * w + 0] = fmaf(p0, f0.x, A[2 * w + 0]);
            A[2 * w + 1] = fmaf(p0, f0.y, A[2 * w + 1]);
            A[2 * w + 0] = fmaf(p1, f1.x, A[2 * w + 0]);
            A[2 * w + 1] = fmaf(p1, f1.y, A[2 * w + 1]);
        }
    }
    for (; j < end; j += 4) {
        int s0 = g_csr[j];
        float e0 = g_as1[s0 * H1 + l];
        uint4 u0 = *(const uint4*)(g_h1h + (long)s0 * HC + l * 8);
        float p0 = __expf(lrelu(e0 + adh));
        sp += p0;
        const __half2* hp0 = (const __half2*)&u0;
        #pragma unroll
        for (int w = 0; w < 4; w++) {
            float2 f0 = __half22float2(hp0[w]);
            A[2 * w + 0] = fmaf(p0, f0.x, A[2 * w + 0]);
            A[2 * w + 1] = fmaf(p0, f0.y, A[2 * w + 1]);
        }
    }
    #pragma unroll
    for (int i = 0; i < 8; i++) {
        A[i] += __shfl_xor_sync(0xffffffffu, A[i], 8);
        A[i] += __shfl_xor_sync(0xffffffffu, A[i], 16);
    }
    sp += __shfl_xor_sync(0xffffffffu, sp, 8);
    sp += __shfl_xor_sync(0xffffffffu, sp, 16);

    if (qt == 0) {
        float inv = 1.0f / (sp + 1e-16f);
        float4 b0 = *(const float4*)(b1 + l * 8);
        float4 b1v = *(const float4*)(b1 + l * 8 + 4);
        float o[8];
        o[0] = A[0] * inv + b0.x; o[1] = A[1] * inv + b0.y;
        o[2] = A[2] * inv + b0.z; o[3] = A[3] * inv + b0.w;
        o[4] = A[4] * inv + b1v.x; o[5] = A[5] * inv + b1v.y;
        o[6] = A[6] * inv + b1v.z; o[7] = A[7] * inv + b1v.w;
        #pragma unroll
        for (int i = 0; i < 8; i++) o[i] = o[i] > 0.f ? o[i] : (expf(o[i]) - 1.f);
        float* op = g_o1 + (long)n * HC + l * 8;
        *(float4*)(op + 0) = make_float4(o[0], o[1], o[2], o[3]);
        *(float4*)(op + 4) = make_float4(o[4], o[5], o[6], o[7]);
    }
}

// ---------------- GEMM2 + fused alpha2 ----------------
__global__ void k_gemm2(const float* __restrict__ W2,
                        const float* __restrict__ a_s, const float* __restrict__ a_d) {
    __shared__ float Ws[HC * NC];
    __shared__ float rows[32 * HC];
    __shared__ float zsm[32 * 41];
    const int t = threadIdx.x;
    const int base = blockIdx.x * 32;
    for (int i = t; i < HC * NC; i += 256) Ws[i] = W2[i];
    for (int i = t; i < 32 * HC; i += 256) {
        int r = i / HC, k = i % HC;
        int gn = base + r;
        rows[i] = (gn < NN) ? g_o1[(long)gn * HC + k] : 0.0f;
    }
    __syncthreads();
    for (int o = t; o < 32 * NC; o += 256) {
        int r = o / NC, c = o % NC;
        int gn = base + r;
        float acc = 0.f;
        const float* rp = rows + r * HC;
        #pragma unroll
        for (int k = 0; k < HC; k++) acc = fmaf(rp[k], Ws[k * NC + c], acc);
        zsm[r * 41 + c] = acc;
        if (gn < NN) g_z[(long)gn * NC + c] = acc;
    }
    __syncthreads();
    if (t < 32) {
        int gn = base + t;
        if (gn < NN) {
            float s = 0.f, d = 0.f;
            #pragma unroll
            for (int c = 0; c < NC; c++) {
                float v = zsm[t * 41 + c];
                s = fmaf(v, a_s[c], s);
                d = fmaf(v, a_d[c], d);
            }
            g_as2[gn] = s;
            g_ad2[gn] = d;
        }
    }
}

// ---------------- layer-2 CSR aggregation + log_softmax: half-warp per edge ----------------
__global__ void k_agg2(float* __restrict__ out, const float* __restrict__ b2) {
    int warp = (blockIdx.x * blockDim.x + threadIdx.x) >> 5;
    if (warp >= NN) return;
    int lane = threadIdx.x & 31;
    int half = lane >> 4;
    int l = lane & 15;
    int n = warp;
    float ad = g_ad2[n];
    int beg = g_row[n], end = g_row[n + 1];
    bool ldz = (l < 10);
    float sp = 0.f;
    float A[4] = {0.f, 0.f, 0.f, 0.f};

    int j = beg + half;
    for (; j + 2 < end; j += 4) {
        int s0 = g_csr[j], s1 = g_csr[j + 2];
        float e0 = g_as2[s0], e1 = g_as2[s1];
        float4 v0 = make_float4(0.f, 0.f, 0.f, 0.f), v1 = v0;
        if (ldz) {
            v0 = *(const float4*)(g_z + (long)s0 * NC + l * 4);
            v1 = *(const float4*)(g_z + (long)s1 * NC + l * 4);
        }
        float p0 = __expf(lrelu(e0 + ad));
        float p1 = __expf(lrelu(e1 + ad));
        sp += p0 + p1;
        A[0] = fmaf(p0, v0.x, A[0]); A[1] = fmaf(p0, v0.y, A[1]);
        A[2] = fmaf(p0, v0.z, A[2]); A[3] = fmaf(p0, v0.w, A[3]);
        A[0] = fmaf(p1, v1.x, A[0]); A[1] = fmaf(p1, v1.y, A[1]);
        A[2] = fmaf(p1, v1.z, A[2]); A[3] = fmaf(p1, v1.w, A[3]);
    }
    for (; j < end; j += 2) {
        int s0 = g_csr[j];
        float e0 = g_as2[s0];
        float4 v0 = make_float4(0.f, 0.f, 0.f, 0.f);
        if (ldz) v0 = *(const float4*)(g_z + (long)s0 * NC + l * 4);
        float p0 = __expf(lrelu(e0 + ad));
        sp += p0;
        A[0] = fmaf(p0, v0.x, A[0]); A[1] = fmaf(p0, v0.y, A[1]);
        A[2] = fmaf(p0, v0.z, A[2]); A[3] = fmaf(p0, v0.w, A[3]);
    }
    #pragma unroll
    for (int i = 0; i < 4; i++) A[i] += __shfl_xor_sync(0xffffffffu, A[i], 16);
    sp += __shfl_xor_sync(0xffffffffu, sp, 16);

    bool act = (half == 0) && ldz;
    float inv = 1.0f / (sp + 1e-16f);
    float v[4];
    float mloc = -3.402823466e38f;
    if (act) {
        float4 bb = *(const float4*)(b2 + l * 4);
        v[0] = A[0] * inv + bb.x; v[1] = A[1] * inv + bb.y;
        v[2] = A[2] * inv + bb.z; v[3] = A[3] * inv + bb.w;
        mloc = fmaxf(fmaxf(v[0], v[1]), fmaxf(v[2], v[3]));
    }
    float m = mloc;
    #pragma unroll
    for (int off = 16; off > 0; off >>= 1)
        m = fmaxf(m, __shfl_xor_sync(0xffffffffu, m, off));
    float sloc = 0.f;
    if (act)
        sloc = expf(v[0] - m) + expf(v[1] - m) + expf(v[2] - m) + expf(v[3] - m);
    float s = sloc;
    #pragma unroll
    for (int off = 16; off > 0; off >>= 1)
        s += __shfl_xor_sync(0xffffffffu, s, off);
    float lse = m + logf(s);
    if (act) {
        float* op = out + (long)n * NC + l * 4;
        *(float4*)op = make_float4(v[0] - lse, v[1] - lse, v[2] - lse, v[3] - lse);
    }
}

// ---------------- launch: fork-join two independent chains ----------------
extern "C" void kernel_launch(void* const* d_in, const int* in_sizes, int n_in,
                              void* d_out, int out_size) {
    const float* x    = (const float*)d_in[0];
    const void*  ei   = d_in[1];
    const float* W1   = (const float*)d_in[2];
    const float* as1  = (const float*)d_in[3];
    const float* ad1  = (const float*)d_in[4];
    const float* b1   = (const float*)d_in[5];
    const float* W2   = (const float*)d_in[6];
    const float* as2  = (const float*)d_in[7];
    const float* ad2  = (const float*)d_in[8];
    const float* b2   = (const float*)d_in[9];
    float*       out  = (float*)d_out;

    static cudaStream_t s2 = 0;
    static cudaEvent_t evFork = 0, evJoin = 0;
    if (s2 == 0) {
        cudaStreamCreateWithFlags(&s2, cudaStreamNonBlocking);
        cudaEventCreateWithFlags(&evFork, cudaEventDisableTiming);
        cudaEventCreateWithFlags(&evJoin, cudaEventDisableTiming);
        cudaFuncSetAttribute(k_gemm1, cudaFuncAttributeMaxDynamicSharedMemorySize, SMEM_G1);
    }

    const int TB = 256;

    // fork
    cudaEventRecord(evFork, 0);
    cudaStreamWaitEvent(s2, evFork, 0);

    // chain B (side stream): CSR build
    k_init   <<<(NN + TB - 1) / TB, TB, 0, s2>>>(ei);
    k_convert<<<(ETOT + TB - 1) / TB, TB, 0, s2>>>(ei);
    k_scan1  <<<NBLK, 1024, 0, s2>>>();
    k_scan2  <<<1, 32, 0, s2>>>();
    k_scan3  <<<(NN + TB - 1) / TB, TB, 0, s2>>>();
    k_scatter<<<(ETOT + TB - 1) / TB, TB, 0, s2>>>();
    cudaEventRecord(evJoin, s2);

    // chain A (origin stream): dense transform, concurrent with chain B
    k_prepW  <<<(FIN * HC + TB - 1) / TB, TB>>>(W1);
    k_gemm1  <<<(NN + 127) / 128, 256, SMEM_G1>>>(x, as1, ad1);

    // join
    cudaStreamWaitEvent(0, evJoin, 0);

    // serial tail
    k_agg1   <<<(NN * 32 + TB - 1) / TB, TB>>>(b1);
    k_gemm2  <<<(NN + 31) / 32, 256>>>(W2, as2, ad2);
    k_agg2   <<<(NN * 32 + TB - 1) / TB, TB>>>(out, b2);
}

// round 14
// speedup vs baseline: 1.3035x; 1.1035x over previous
#include <cuda_runtime.h>
#include <cuda_bf16.h>
#include <cuda_fp16.h>
#include <math.h>

#define NN 100000
#define EE 1600000
#define FIN 512
#define H1 8
#define C1 8
#define HC 64
#define NC 40
#define ETOT (EE + NN)
#define NEG_SLOPE 0.2f
#define NBLK 98   // ceil(NN/1024)

// ---------------- scratch ----------------
__device__ unsigned short g_h1h[NN * HC];   // layer-1 features, fp16 (consumer: agg1)
__device__ unsigned short g_o1h[NN * HC];   // layer-1 output h2, fp16 (consumer: agg2)
__device__ float g_as1[NN * H1];
__device__ float g_ad1[NN * H1];
__device__ float g_as2[NN];
__device__ float g_ad2[NN];
__device__ float g_ws[HC];                  // W2 @ a_src2
__device__ float g_wd[HC];                  // W2 @ a_dst2
__device__ int   g_src[ETOT];
__device__ int   g_dst[ETOT];
__device__ int   g_deg[NN];
__device__ int   g_row[NN + 1];
__device__ int   g_cursor[NN];
__device__ int   g_bsum[NBLK];
__device__ int   g_csr[ETOT];
__device__ int   g_is64 = 1;   // monotone flag, converges identically every call
__device__ unsigned short g_W1T_hi[HC * FIN];
__device__ unsigned short g_W1T_lo[HC * FIN];

__device__ __forceinline__ float lrelu(float x) {
    return x > 0.0f ? x : NEG_SLOPE * x;
}

__device__ __forceinline__ void split_bf16(float v, unsigned short& hi, unsigned short& lo) {
    __nv_bfloat16 h = __float2bfloat16(v);
    float r = v - __bfloat162float(h);
    __nv_bfloat16 l = __float2bfloat16(r);
    hi = __bfloat16_as_ushort(h);
    lo = __bfloat16_as_ushort(l);
}

__device__ __forceinline__ void mma_bf16(float* c, const unsigned* a, const unsigned* b) {
    asm volatile(
        "mma.sync.aligned.m16n8k16.row.col.f32.bf16.bf16.f32 "
        "{%0,%1,%2,%3},{%4,%5,%6,%7},{%8,%9},{%0,%1,%2,%3};"
        : "+f"(c[0]), "+f"(c[1]), "+f"(c[2]), "+f"(c[3])
        : "r"(a[0]), "r"(a[1]), "r"(a[2]), "r"(a[3]), "r"(b[0]), "r"(b[1]));
}

__device__ __forceinline__ void ldsm4(unsigned* r, unsigned addr) {
    asm volatile("ldmatrix.sync.aligned.m8n8.x4.shared.b16 {%0,%1,%2,%3}, [%4];"
                 : "=r"(r[0]), "=r"(r[1]), "=r"(r[2]), "=r"(r[3]) : "r"(addr));
}

// ---------------- init + dtype probe ----------------
__global__ void k_init(const void* __restrict__ ei) {
    int i = blockIdx.x * blockDim.x + threadIdx.x;
    if (i < NN) g_deg[i] = 0;
    if (i < 2048) {
        long long v = ((const long long*)ei)[i];
        if (v < 0 || v >= NN) atomicAnd(&g_is64, 0);
    }
}

// ---------------- edge conversion + degree count ----------------
__global__ void k_convert(const void* __restrict__ ei) {
    int idx = blockIdx.x * blockDim.x + threadIdx.x;
    if (idx >= ETOT) return;
    int s, d;
    if (idx < EE) {
        if (g_is64) {
            const long long* p = (const long long*)ei;
            s = (int)p[idx];
            d = (int)p[EE + idx];
        } else {
            const int* p = (const int*)ei;
            s = p[idx];
            d = p[EE + idx];
        }
    } else {
        s = d = idx - EE;
    }
    s = min(max(s, 0), NN - 1);
    d = min(max(d, 0), NN - 1);
    g_src[idx] = s;
    g_dst[idx] = d;
    atomicAdd(&g_deg[d], 1);
}

// ---------------- exclusive scan of degrees ----------------
__global__ void k_scan1() {
    __shared__ int sh[1024];
    int tid = threadIdx.x;
    int i = blockIdx.x * 1024 + tid;
    int v = (i < NN) ? g_deg[i] : 0;
    sh[tid] = v;
    __syncthreads();
    #pragma unroll
    for (int off = 1; off < 1024; off <<= 1) {
        int t = (tid >= off) ? sh[tid - off] : 0;
        __syncthreads();
        sh[tid] += t;
        __syncthreads();
    }
    if (i < NN) g_row[i] = sh[tid] - v;
    if (tid == 1023) g_bsum[blockIdx.x] = sh[1023];
}

__global__ void k_scan2() {
    if (threadIdx.x == 0) {
        int acc = 0;
        for (int b = 0; b < NBLK; b++) { int t = g_bsum[b]; g_bsum[b] = acc; acc += t; }
        g_row[NN] = acc;
    }
}

__global__ void k_scan3() {
    int i = blockIdx.x * blockDim.x + threadIdx.x;
    if (i < NN) {
        int r = g_row[i] + g_bsum[i >> 10];
        g_row[i] = r;
        g_cursor[i] = r;
    }
}

__global__ void k_scatter() {
    int idx = blockIdx.x * blockDim.x + threadIdx.x;
    if (idx >= ETOT) return;
    int d = g_dst[idx];
    int pos = atomicAdd(&g_cursor[d], 1);
    g_csr[pos] = g_src[idx];
}

// ---------------- W1 split/transpose ----------------
__global__ void k_prepW(const float* __restrict__ W1) {
    int i = blockIdx.x * blockDim.x + threadIdx.x;
    if (i >= FIN * HC) return;
    int k = i / HC, n = i % HC;
    unsigned short hi, lo;
    split_bf16(W1[i], hi, lo);
    g_W1T_hi[n * FIN + k] = hi;
    g_W1T_lo[n * FIN + k] = lo;
}

// ---------------- w_s = W2 @ a_src2, w_d = W2 @ a_dst2 (layer-2 logit folding) ----------------
__global__ void k_wsd(const float* __restrict__ W2,
                      const float* __restrict__ a_s2, const float* __restrict__ a_d2) {
    int k = threadIdx.x;
    if (k < HC) {
        float s = 0.f, d = 0.f;
        #pragma unroll
        for (int c = 0; c < NC; c++) {
            float w = W2[k * NC + c];
            s = fmaf(w, a_s2[c], s);
            d = fmaf(w, a_d2[c], d);
        }
        g_ws[k] = s;
        g_wd[k] = d;
    }
}

// ---------------- GEMM1: bf16x3 tensor cores, ldmatrix, ping-pong pipeline ----------------
#define ASTR 40
#define ABYT (128 * ASTR * 2)   // 10240 B per A buffer
#define BBYT (64 * ASTR * 2)    // 5120 B per B buffer
#define OFF_AH(b) ((b) * ABYT)
#define OFF_AL(b) (2 * ABYT + (b) * ABYT)
#define OFF_BH(b) (4 * ABYT + (b) * BBYT)
#define OFF_BL(b) (4 * ABYT + 2 * BBYT + (b) * BBYT)
#define SMEM_G1  (4 * ABYT + 4 * BBYT)   // 61440 B

__global__ __launch_bounds__(256, 2) void k_gemm1(const float* __restrict__ x,
                                                  const float* __restrict__ a_s,
                                                  const float* __restrict__ a_d) {
    extern __shared__ __align__(16) char sm[];
    const unsigned smu = (unsigned)__cvta_generic_to_shared(sm);

    const int t = threadIdx.x;
    const int bm0 = blockIdx.x * 128;
    const int warp = t >> 5;
    const int lane = t & 31;
    const int g = lane >> 2;
    const int q = lane & 3;
    const int warp_m = warp >> 1;
    const int warp_n = warp & 1;
    const int brow = t >> 2;
    const int bseg = t & 3;

    const int mat = lane >> 3;
    const int rowin = lane & 7;
    const int lm_off = ((mat & 1) * 8 + rowin) * ASTR + (mat >> 1) * 8;  // elements

    float acc[2][4][4];
    #pragma unroll
    for (int i = 0; i < 2; i++)
        #pragma unroll
        for (int j = 0; j < 4; j++)
            #pragma unroll
            for (int r = 0; r < 4; r++) acc[i][j][r] = 0.f;

    float4 ra[4];
    uint4 rbh, rbl;

    auto load_regs = [&](int k0) {
        #pragma unroll
        for (int i = 0; i < 4; i++) {
            int idx = i * 256 + t;
            int row = idx >> 3;
            int col = (idx & 7) * 4;
            int gr = bm0 + row;
            ra[i] = (gr < NN) ? *(const float4*)(x + (long)gr * FIN + k0 + col)
                              : make_float4(0.f, 0.f, 0.f, 0.f);
        }
        rbh = *(const uint4*)&g_W1T_hi[brow * FIN + k0 + bseg * 8];
        rbl = *(const uint4*)&g_W1T_lo[brow * FIN + k0 + bseg * 8];
    };

    auto store_smem = [&](int b) {
        unsigned short* AsH = (unsigned short*)(sm + OFF_AH(b));
        unsigned short* AsL = (unsigned short*)(sm + OFF_AL(b));
        unsigned short* BsH = (unsigned short*)(sm + OFF_BH(b));
        unsigned short* BsL = (unsigned short*)(sm + OFF_BL(b));
        #pragma unroll
        for (int i = 0; i < 4; i++) {
            int idx = i * 256 + t;
            int row = idx >> 3;
            int col = (idx & 7) * 4;
            unsigned short h0, l0, h1_, l1_, h2, l2, h3, l3;
            split_bf16(ra[i].x, h0, l0);
            split_bf16(ra[i].y, h1_, l1_);
            split_bf16(ra[i].z, h2, l2);
            split_bf16(ra[i].w, h3, l3);
            unsigned* ph = (unsigned*)&AsH[row * ASTR + col];
            unsigned* pl = (unsigned*)&AsL[row * ASTR + col];
            ph[0] = (unsigned)h0 | ((unsigned)h1_ << 16);
            ph[1] = (unsigned)h2 | ((unsigned)h3 << 16);
            pl[0] = (unsigned)l0 | ((unsigned)l1_ << 16);
            pl[1] = (unsigned)l2 | ((unsigned)l3 << 16);
        }
        *(uint4*)&BsH[brow * ASTR + bseg * 8] = rbh;
        *(uint4*)&BsL[brow * ASTR + bseg * 8] = rbl;
    };

    load_regs(0);
    store_smem(0);

    for (int kt = 0; kt < FIN / 32; kt++) {
        const int cur = kt & 1;
        __syncthreads();
        if (kt + 1 < FIN / 32) load_regs((kt + 1) * 32);

        const unsigned ash = smu + OFF_AH(cur);
        const unsigned asl = smu + OFF_AL(cur);
        const unsigned bsh = smu + OFF_BH(cur);
        const unsigned bsl = smu + OFF_BL(cur);

        #pragma unroll
        for (int ka = 0; ka < 2; ka++) {
            const int kc = ka * 16;
            unsigned a_hi[2][4], a_lo[2][4], b_hi[4][2], b_lo[4][2];
            #pragma unroll
            for (int ma = 0; ma < 2; ma++) {
                int r0 = warp_m * 32 + ma * 16;
                unsigned eoff = (unsigned)((r0 * ASTR + kc + lm_off) * 2);
                ldsm4(a_hi[ma], ash + eoff);
                ldsm4(a_lo[ma], asl + eoff);
            }
            #pragma unroll
            for (int p = 0; p < 2; p++) {
                int n0 = warp_n * 32 + p * 16;
                unsigned eoff = (unsigned)((n0 * ASTR + kc + lm_off) * 2);
                unsigned rh[4], rl[4];
                ldsm4(rh, bsh + eoff);
                ldsm4(rl, bsl + eoff);
                b_hi[2 * p][0] = rh[0]; b_hi[2 * p][1] = rh[2];
                b_hi[2 * p + 1][0] = rh[1]; b_hi[2 * p + 1][1] = rh[3];
                b_lo[2 * p][0] = rl[0]; b_lo[2 * p][1] = rl[2];
                b_lo[2 * p + 1][0] = rl[1]; b_lo[2 * p + 1][1] = rl[3];
            }
            #pragma unroll
            for (int ma = 0; ma < 2; ma++)
                #pragma unroll
                for (int na = 0; na < 4; na++) {
                    mma_bf16(acc[ma][na], a_hi[ma], b_hi[na]);
                    mma_bf16(acc[ma][na], a_hi[ma], b_lo[na]);
                    mma_bf16(acc[ma][na], a_lo[ma], b_hi[na]);
                }
        }

        if (kt + 1 < FIN / 32) store_smem(cur ^ 1);
    }

    // ---- epilogue: write h1 as fp16 ----
    #pragma unroll
    for (int ma = 0; ma < 2; ma++) {
        int r0 = bm0 + warp_m * 32 + ma * 16 + g;
        #pragma unroll
        for (int na = 0; na < 4; na++) {
            int c = warp_n * 32 + na * 8 + 2 * q;
            if (r0 < NN)
                *(__half2*)(g_h1h + (long)r0 * HC + c) =
                    __floats2half2_rn(acc[ma][na][0], acc[ma][na][1]);
            if (r0 + 8 < NN)
                *(__half2*)(g_h1h + (long)(r0 + 8) * HC + c) =
                    __floats2half2_rn(acc[ma][na][2], acc[ma][na][3]);
        }
    }

    // ---- fused alpha1 ----
    float as_c0[4], as_c1[4], ad_c0[4], ad_c1[4];
    #pragma unroll
    for (int na = 0; na < 4; na++) {
        int hh = warp_n * 4 + na;
        as_c0[na] = a_s[hh * 8 + 2 * q];
        as_c1[na] = a_s[hh * 8 + 2 * q + 1];
        ad_c0[na] = a_d[hh * 8 + 2 * q];
        ad_c1[na] = a_d[hh * 8 + 2 * q + 1];
    }
    #pragma unroll
    for (int ma = 0; ma < 2; ma++)
        #pragma unroll
        for (int rh = 0; rh < 2; rh++) {
            float s[4], d[4];
            #pragma unroll
            for (int na = 0; na < 4; na++) {
                float h0 = acc[ma][na][rh * 2 + 0];
                float h1v = acc[ma][na][rh * 2 + 1];
                s[na] = h0 * as_c0[na] + h1v * as_c1[na];
                d[na] = h0 * ad_c0[na] + h1v * ad_c1[na];
            }
            #pragma unroll
            for (int na = 0; na < 4; na++) {
                s[na] += __shfl_xor_sync(0xffffffffu, s[na], 1);
                s[na] += __shfl_xor_sync(0xffffffffu, s[na], 2);
                d[na] += __shfl_xor_sync(0xffffffffu, d[na], 1);
                d[na] += __shfl_xor_sync(0xffffffffu, d[na], 2);
            }
            int row = bm0 + warp_m * 32 + ma * 16 + rh * 8 + g;
            if (q == 0 && row < NN) {
                *(float4*)(g_as1 + row * H1 + warp_n * 4) = make_float4(s[0], s[1], s[2], s[3]);
                *(float4*)(g_ad1 + row * H1 + warp_n * 4) = make_float4(d[0], d[1], d[2], d[3]);
            }
        }
}

// ---------------- layer-1 CSR aggregation + ELU + fused alpha2 ----------------
// quarter-warp per edge; lane l owns head l = channels 8l..8l+7 (fp16 rows).
// After the xor butterfly ALL lanes hold the full aggregate -> alpha2 dots are free.
__global__ void k_agg1(const float* __restrict__ b1) {
    int warp = (blockIdx.x * blockDim.x + threadIdx.x) >> 5;
    if (warp >= NN) return;
    int lane = threadIdx.x & 31;
    int qt = lane >> 3;
    int l = lane & 7;
    int n = warp;
    float adh = g_ad1[n * H1 + l];
    int beg = g_row[n], end = g_row[n + 1];
    float sp = 0.f;
    float A[8] = {0.f, 0.f, 0.f, 0.f, 0.f, 0.f, 0.f, 0.f};

    int j = beg + qt;
    for (; j + 4 < end; j += 8) {
        int s0 = g_csr[j], s1 = g_csr[j + 4];
        float e0 = g_as1[s0 * H1 + l];
        float e1 = g_as1[s1 * H1 + l];
        uint4 u0 = *(const uint4*)(g_h1h + (long)s0 * HC + l * 8);
        uint4 u1 = *(const uint4*)(g_h1h + (long)s1 * HC + l * 8);
        float p0 = __expf(lrelu(e0 + adh));
        float p1 = __expf(lrelu(e1 + adh));
        sp += p0 + p1;
        const __half2* hp0 = (const __half2*)&u0;
        const __half2* hp1 = (const __half2*)&u1;
        #pragma unroll
        for (int w = 0; w < 4; w++) {
            float2 f0 = __half22float2(hp0[w]);
            float2 f1 = __half22float2(hp1[w]);
            A[2 * w + 0] = fmaf(p0, f0.x, A[2 * w + 0]);
            A[2 * w + 1] = fmaf(p0, f0.y, A[2 * w + 1]);
            A[2 * w + 0] = fmaf(p1, f1.x, A[2 * w + 0]);
            A[2 * w + 1] = fmaf(p1, f1.y, A[2 * w + 1]);
        }
    }
    for (; j < end; j += 4) {
        int s0 = g_csr[j];
        float e0 = g_as1[s0 * H1 + l];
        uint4 u0 = *(const uint4*)(g_h1h + (long)s0 * HC + l * 8);
        float p0 = __expf(lrelu(e0 + adh));
        sp += p0;
        const __half2* hp0 = (const __half2*)&u0;
        #pragma unroll
        for (int w = 0; w < 4; w++) {
            float2 f0 = __half22float2(hp0[w]);
            A[2 * w + 0] = fmaf(p0, f0.x, A[2 * w + 0]);
            A[2 * w + 1] = fmaf(p0, f0.y, A[2 * w + 1]);
        }
    }
    #pragma unroll
    for (int i = 0; i < 8; i++) {
        A[i] += __shfl_xor_sync(0xffffffffu, A[i], 8);
        A[i] += __shfl_xor_sync(0xffffffffu, A[i], 16);
    }
    sp += __shfl_xor_sync(0xffffffffu, sp, 8);
    sp += __shfl_xor_sync(0xffffffffu, sp, 16);

    // epilogue computed in ALL lanes (quarters hold identical values)
    float inv = 1.0f / (sp + 1e-16f);
    float4 b0 = *(const float4*)(b1 + l * 8);
    float4 b1v = *(const float4*)(b1 + l * 8 + 4);
    float o[8];
    o[0] = A[0] * inv + b0.x; o[1] = A[1] * inv + b0.y;
    o[2] = A[2] * inv + b0.z; o[3] = A[3] * inv + b0.w;
    o[4] = A[4] * inv + b1v.x; o[5] = A[5] * inv + b1v.y;
    o[6] = A[6] * inv + b1v.z; o[7] = A[7] * inv + b1v.w;
    #pragma unroll
    for (int i = 0; i < 8; i++) o[i] = o[i] > 0.f ? o[i] : (expf(o[i]) - 1.f);

    if (qt == 0) {
        // store h2 as fp16
        __half2 hv[4];
        #pragma unroll
        for (int w = 0; w < 4; w++) hv[w] = __floats2half2_rn(o[2 * w], o[2 * w + 1]);
        *(uint4*)(g_o1h + (long)n * HC + l * 8) = *(uint4*)hv;
    }

    // fused alpha2: as2[n] = o . w_s, ad2[n] = o . w_d (fp32 o, exact)
    float ps = 0.f, pd = 0.f;
    #pragma unroll
    for (int i = 0; i < 8; i++) {
        ps = fmaf(o[i], g_ws[l * 8 + i], ps);
        pd = fmaf(o[i], g_wd[l * 8 + i], pd);
    }
    ps += __shfl_xor_sync(0xffffffffu, ps, 1);
    ps += __shfl_xor_sync(0xffffffffu, ps, 2);
    ps += __shfl_xor_sync(0xffffffffu, ps, 4);
    pd += __shfl_xor_sync(0xffffffffu, pd, 1);
    pd += __shfl_xor_sync(0xffffffffu, pd, 2);
    pd += __shfl_xor_sync(0xffffffffu, pd, 4);
    if (lane == 0) {
        g_as2[n] = ps;
        g_ad2[n] = pd;
    }
}

// ---------------- layer-2: aggregate o over edges, then matvec W2 + log_softmax ----------------
// quarter-warp per edge on fp16 o rows; epilogue does (A/sp).W2 + b2 then log_softmax.
__global__ void k_agg2(float* __restrict__ out, const float* __restrict__ b2,
                       const float* __restrict__ W2) {
    __shared__ float W2s[HC * NC];    // 10240 B
    __shared__ float buf[8][HC];      // 2048 B (one 64-vec per warp)
    const int t = threadIdx.x;
    for (int i = t; i < HC * NC; i += 256) W2s[i] = W2[i];
    __syncthreads();

    int warp = (blockIdx.x * blockDim.x + t) >> 5;
    if (warp >= NN) return;
    int wloc = t >> 5;
    int lane = t & 31;
    int qt = lane >> 3;
    int l = lane & 7;
    int n = warp;
    float ad = g_ad2[n];
    int beg = g_row[n], end = g_row[n + 1];
    float sp = 0.f;
    float A[8] = {0.f, 0.f, 0.f, 0.f, 0.f, 0.f, 0.f, 0.f};

    int j = beg + qt;
    for (; j + 4 < end; j += 8) {
        int s0 = g_csr[j], s1 = g_csr[j + 4];
        float e0 = g_as2[s0], e1 = g_as2[s1];
        uint4 u0 = *(const uint4*)(g_o1h + (long)s0 * HC + l * 8);
        uint4 u1 = *(const uint4*)(g_o1h + (long)s1 * HC + l * 8);
        float p0 = __expf(lrelu(e0 + ad));
        float p1 = __expf(lrelu(e1 + ad));
        sp += p0 + p1;
        const __half2* hp0 = (const __half2*)&u0;
        const __half2* hp1 = (const __half2*)&u1;
        #pragma unroll
        for (int w = 0; w < 4; w++) {
            float2 f0 = __half22float2(hp0[w]);
            float2 f1 = __half22float2(hp1[w]);
            A[2 * w + 0] = fmaf(p0, f0.x, A[2 * w + 0]);
            A[2 * w + 1] = fmaf(p0, f0.y, A[2 * w + 1]);
            A[2 * w + 0] = fmaf(p1, f1.x, A[2 * w + 0]);
            A[2 * w + 1] = fmaf(p1, f1.y, A[2 * w + 1]);
        }
    }
    for (; j < end; j += 4) {
        int s0 = g_csr[j];
        float e0 = g_as2[s0];
        uint4 u0 = *(const uint4*)(g_o1h + (long)s0 * HC + l * 8);
        float p0 = __expf(lrelu(e0 + ad));
        sp += p0;
        const __half2* hp0 = (const __half2*)&u0;
        #pragma unroll
        for (int w = 0; w < 4; w++) {
            float2 f0 = __half22float2(hp0[w]);
            A[2 * w + 0] = fmaf(p0, f0.x, A[2 * w + 0]);
            A[2 * w + 1] = fmaf(p0, f0.y, A[2 * w + 1]);
        }
    }
    #pragma unroll
    for (int i = 0; i < 8; i++) {
        A[i] += __shfl_xor_sync(0xffffffffu, A[i], 8);
        A[i] += __shfl_xor_sync(0xffffffffu, A[i], 16);
    }
    sp += __shfl_xor_sync(0xffffffffu, sp, 8);
    sp += __shfl_xor_sync(0xffffffffu, sp, 16);

    float inv = 1.0f / (sp + 1e-16f);
    if (lane < 8) {
        #pragma unroll
        for (int i = 0; i < 8; i++) buf[wloc][l * 8 + i] = A[i] * inv;
    }
    __syncwarp();

    // matvec: va = aggregate . W2[:, lane], vb = aggregate . W2[:, 32+lane] (lane<8)
    float va = 0.f, vb = 0.f;
    #pragma unroll 8
    for (int k = 0; k < HC; k++) {
        float bk = buf[wloc][k];
        va = fmaf(bk, W2s[k * NC + lane], va);
        if (lane < 8) vb = fmaf(bk, W2s[k * NC + 32 + lane], vb);
    }
    va += b2[lane];
    vb = (lane < 8) ? vb + b2[32 + lane] : -3.402823466e38f;

    float m = fmaxf(va, vb);
    #pragma unroll
    for (int off = 16; off > 0; off >>= 1)
        m = fmaxf(m, __shfl_xor_sync(0xffffffffu, m, off));
    float s = expf(va - m) + ((lane < 8) ? expf(vb - m) : 0.f);
    #pragma unroll
    for (int off = 16; off > 0; off >>= 1)
        s += __shfl_xor_sync(0xffffffffu, s, off);
    float lse = m + logf(s);
    float* op = out + (long)n * NC;
    op[lane] = va - lse;
    if (lane < 8) op[32 + lane] = vb - lse;
}

// ---------------- launch: fork-join two independent chains ----------------
extern "C" void kernel_launch(void* const* d_in, const int* in_sizes, int n_in,
                              void* d_out, int out_size) {
    const float* x    = (const float*)d_in[0];
    const void*  ei   = d_in[1];
    const float* W1   = (const float*)d_in[2];
    const float* as1  = (const float*)d_in[3];
    const float* ad1  = (const float*)d_in[4];
    const float* b1   = (const float*)d_in[5];
    const float* W2   = (const float*)d_in[6];
    const float* as2  = (const float*)d_in[7];
    const float* ad2  = (const float*)d_in[8];
    const float* b2   = (const float*)d_in[9];
    float*       out  = (float*)d_out;

    static cudaStream_t s2 = 0;
    static cudaEvent_t evFork = 0, evJoin = 0;
    if (s2 == 0) {
        cudaStreamCreateWithFlags(&s2, cudaStreamNonBlocking);
        cudaEventCreateWithFlags(&evFork, cudaEventDisableTiming);
        cudaEventCreateWithFlags(&evJoin, cudaEventDisableTiming);
        cudaFuncSetAttribute(k_gemm1, cudaFuncAttributeMaxDynamicSharedMemorySize, SMEM_G1);
    }

    const int TB = 256;

    // fork
    cudaEventRecord(evFork, 0);
    cudaStreamWaitEvent(s2, evFork, 0);

    // chain B (side stream): CSR build
    k_init   <<<(NN + TB - 1) / TB, TB, 0, s2>>>(ei);
    k_convert<<<(ETOT + TB - 1) / TB, TB, 0, s2>>>(ei);
    k_scan1  <<<NBLK, 1024, 0, s2>>>();
    k_scan2  <<<1, 32, 0, s2>>>();
    k_scan3  <<<(NN + TB - 1) / TB, TB, 0, s2>>>();
    k_scatter<<<(ETOT + TB - 1) / TB, TB, 0, s2>>>();
    cudaEventRecord(evJoin, s2);

    // chain A (origin stream): dense transform, concurrent with chain B
    k_prepW  <<<(FIN * HC + TB - 1) / TB, TB>>>(W1);
    k_wsd    <<<1, 64>>>(W2, as2, ad2);
    k_gemm1  <<<(NN + 127) / 128, 256, SMEM_G1>>>(x, as1, ad1);

    // join
    cudaStreamWaitEvent(0, evJoin, 0);

    // serial tail (gemm2 algebraically eliminated)
    k_agg1   <<<(NN * 32 + TB - 1) / TB, TB>>>(b1);
    k_agg2   <<<(NN * 32 + TB - 1) / TB, TB>>>(out, b2, W2);
}